// round 9
// baseline (speedup 1.0000x reference)
#include <cuda_runtime.h>
#include <cuda_fp16.h>
#include <cstdint>

#define BB 256
#define HH 1024
#define LL 4
#define DKV 512
#define II 4096
#define VV 1027
#define CC 16
#define REPW 50
#define INF_F __int_as_float(0x7f800000)

// ---------------- scratch (device globals; no allocation) ----------------
__device__ float g_h[BB*HH];
__device__ float g_logits[BB*VV];
__device__ float g_woP[LL*DKV*HH];
__device__ float g_part[4210688];              // split-K partials (max 16*256*1027)
__device__ __half g_x2[2*BB*HH];
__device__ __half g_v2[2*BB*DKV];
__device__ __half g_m2[2*BB*II];
__device__ __half g_wv2[(size_t)2*LL*DKV*HH];  // [2][L][N=512][K=1024]
__device__ __half g_wo2[(size_t)2*LL*HH*DKV];  // [2][L][N=1024][K=512]
__device__ __half g_gu2[(size_t)2*LL*8192*HH]; // [2][L][N=8192][K=1024] (gate|up)
__device__ __half g_wd2[(size_t)2*LL*HH*II];   // [2][L][N=1024][K=4096]
__device__ __half g_lm2[(size_t)2*CC*VV*HH];   // [2][C][N=1027][K=1024]

// ---------------- threefry2x32 (JAX exact) ----------------
#define TF_ROUND(x0,x1,r) { x0 += x1; x1 = (x1<<(r))|(x1>>(32-(r))); x1 ^= x0; }
__host__ __device__ __forceinline__ void threefry2x32(unsigned k0, unsigned k1,
                                                      unsigned c0, unsigned c1,
                                                      unsigned* o0, unsigned* o1) {
  unsigned ks2 = k0 ^ k1 ^ 0x1BD11BDAu;
  unsigned x0 = c0 + k0, x1 = c1 + k1;
  TF_ROUND(x0,x1,13) TF_ROUND(x0,x1,15) TF_ROUND(x0,x1,26) TF_ROUND(x0,x1,6)
  x0 += k1;  x1 += ks2 + 1u;
  TF_ROUND(x0,x1,17) TF_ROUND(x0,x1,29) TF_ROUND(x0,x1,16) TF_ROUND(x0,x1,24)
  x0 += ks2; x1 += k0 + 2u;
  TF_ROUND(x0,x1,13) TF_ROUND(x0,x1,15) TF_ROUND(x0,x1,26) TF_ROUND(x0,x1,6)
  x0 += k0;  x1 += k1 + 3u;
  TF_ROUND(x0,x1,17) TF_ROUND(x0,x1,29) TF_ROUND(x0,x1,16) TF_ROUND(x0,x1,24)
  x0 += k1;  x1 += ks2 + 4u;
  TF_ROUND(x0,x1,13) TF_ROUND(x0,x1,15) TF_ROUND(x0,x1,26) TF_ROUND(x0,x1,6)
  x0 += ks2; x1 += k0 + 5u;
  *o0 = x0; *o1 = x1;
}

// ---------------- small kernels ----------------
__global__ void copy_kernel(const float* __restrict__ in, float* __restrict__ out, int n) {
  int i = blockIdx.x*blockDim.x + threadIdx.x;
  if (i < n) out[i] = in[i];
}

__global__ void wop_kernel(const float* __restrict__ wo, float* __restrict__ out) {
  int idx = blockIdx.x*blockDim.x + threadIdx.x;
  if (idx >= LL*DKV*HH) return;
  int l = idx >> 19;
  int rem = idx & 524287;
  int s = rem >> 10, n = rem & 1023;
  int hv = s >> 6, d = s & 63;
  const float* w = wo + ((size_t)l << 20);
  out[idx] = w[((hv*2)*64 + d)*1024 + n] + w[((hv*2+1)*64 + d)*1024 + n];
}

__device__ __forceinline__ void split2(float x, __half& h0, __half& h1) {
  h0 = __float2half_rn(x);
  h1 = __float2half_rn(x - __half2float(h0));
}

// transpose-split: W fp32 [K][N] (layer z) -> O fp16 2 planes of [N][K]
__global__ void tsplit_kernel(const float* __restrict__ W, __half* __restrict__ O,
                              int K, int N, size_t wLS, size_t oLS, size_t plane) {
  __shared__ float tile[32][33];
  const float* Wz = W + (size_t)blockIdx.z * wLS;
  __half* Oz = O + (size_t)blockIdx.z * oLS;
  int kb = blockIdx.y*32, nb = blockIdx.x*32;
  int tx = threadIdx.x, ty = threadIdx.y;
  for (int i = ty; i < 32; i += 8)
    tile[i][tx] = Wz[(size_t)(kb+i)*N + nb + tx];
  __syncthreads();
  for (int i = ty; i < 32; i += 8) {
    __half h0, h1; split2(tile[tx][i], h0, h1);
    size_t o = (size_t)(nb + i)*K + kb + tx;
    Oz[o] = h0; Oz[plane + o] = h1;
  }
}

// plain split (already [N][K])
__global__ void split_kernel(const float* __restrict__ in, __half* __restrict__ O,
                             size_t n, size_t plane) {
  size_t i = (size_t)blockIdx.x*blockDim.x + threadIdx.x;
  if (i >= n) return;
  __half h0, h1; split2(in[i], h0, h1);
  O[i] = h0; O[plane + i] = h1;
}

__global__ void rms2_kernel(const float* __restrict__ in, const float* __restrict__ w,
                            __half* __restrict__ O, size_t plane) {
  int b = blockIdx.x, t = threadIdx.x;
  const float* row = in + (size_t)b*HH;
  __shared__ float red[256];
  float s = 0.f;
  #pragma unroll
  for (int j = t; j < HH; j += 256) { float v = row[j]; s += v*v; }
  red[t] = s; __syncthreads();
  for (int st = 128; st > 0; st >>= 1) { if (t < st) red[t] += red[t+st]; __syncthreads(); }
  float r = 1.0f / sqrtf(red[0]*(1.0f/HH) + 1e-6f);
  for (int j = t; j < HH; j += 256) {
    float y = row[j]*r*w[j];
    __half h0, h1; split2(y, h0, h1);
    size_t o = (size_t)b*HH + j;
    O[o] = h0; O[plane + o] = h1;
  }
}

// flat split-K reduce: fp32 out and/or fp16x2 out (used for v and lm)
__global__ void reduce_kernel(const float* __restrict__ P, float* __restrict__ outF,
                              __half* __restrict__ outS, size_t plane,
                              int S, int MN4) {
  int i = blockIdx.x*blockDim.x + threadIdx.x;
  if (i >= MN4) return;
  const float4* P4 = (const float4*)P;
  float4 s = P4[i];
  for (int t = 1; t < S; t++) {
    float4 p = P4[(size_t)t*MN4 + i];
    s.x += p.x; s.y += p.y; s.z += p.z; s.w += p.w;
  }
  if (outF) ((float4*)outF)[i] = s;
  if (outS) {
    float v[4] = {s.x, s.y, s.z, s.w};
    #pragma unroll
    for (int c = 0; c < 4; c++) {
      __half h0, h1; split2(v[c], h0, h1);
      size_t o = (size_t)i*4 + c;
      outS[o] = h0; outS[plane + o] = h1;
    }
  }
}

// fused: split-K reduce + residual -> h update + RMSNorm -> fp16x2 splits
__global__ void reduce_rms_kernel(const float* __restrict__ P, float* __restrict__ h,
                                  const float* __restrict__ w,
                                  __half* __restrict__ outX, size_t plane, int S) {
  int b = blockIdx.x, t = threadIdx.x;
  __shared__ float row[HH];
  __shared__ float red[256];
  const int MN = BB*HH;
  float sq = 0.f;
  for (int j = t; j < HH; j += 256) {
    float s = h[(size_t)b*HH + j];
    for (int z = 0; z < S; z++) s += P[(size_t)z*MN + b*HH + j];
    row[j] = s;
    h[(size_t)b*HH + j] = s;
    sq += s*s;
  }
  red[t] = sq; __syncthreads();
  for (int st = 128; st > 0; st >>= 1) { if (t < st) red[t] += red[t+st]; __syncthreads(); }
  float r = 1.0f / sqrtf(red[0]*(1.0f/HH) + 1e-6f);
  for (int j = t; j < HH; j += 256) {
    float y = row[j]*r*w[j];
    __half h0, h1; split2(y, h0, h1);
    size_t o = (size_t)b*HH + j;
    outX[o] = h0; outX[plane + o] = h1;
  }
}

// fused gate+up reduce (S=2) + swiglu -> m fp16x2 splits
__global__ void reduce_swiglu_kernel(const float* __restrict__ P,
                                     __half* __restrict__ outM, size_t plane) {
  int i = blockIdx.x*blockDim.x + threadIdx.x;
  if (i >= BB*II) return;
  int b = i >> 12, j = i & (II - 1);
  const size_t MN = (size_t)BB*8192;
  size_t gi = (size_t)b*8192 + j;
  float g = P[gi] + P[MN + gi];
  float u = P[gi + II] + P[MN + gi + II];
  float s = __fdiv_rn(1.f, __fadd_rn(1.f, expf(-g)));
  float m = g*s*u;
  __half h0, h1; split2(m, h0, h1);
  outM[i] = h0; outM[plane + i] = h1;
}

// ---------------- HMMA fp16x2-split GEMM (LDG->reg->STS double buffer) ----------------
// P[z][256][N] = A @ B^T; A2: 2 fp16 planes [M][K]; B2: 2 fp16 planes [N][K].
// 3 products: (a0,b0), (a0,b1), (a1,b0). CTA 128x128, k-chunk 32.
#define ROWB2 80          // 32 halves (64B) + 16B pad
#define PT    10240       // plane tile bytes: 128*80
#define HG_SMEM 81920     // A: 4*PT, B: 4*PT

__global__ void __launch_bounds__(256, 2)
hgemm_kernel(const __half* __restrict__ A2, const size_t aplane,
             const __half* __restrict__ B2, const size_t bplane,
             float* __restrict__ P, const int N, const int K) {
  extern __shared__ char smem[];
  uint32_t smbase;
  asm("{ .reg .u64 t; cvta.to.shared.u64 t, %1; cvt.u32.u64 %0, t; }"
      : "=r"(smbase) : "l"(smem));

  const int tid = threadIdx.x, wid = tid >> 5, lid = tid & 31;
  const int wm = wid & 1, wn = wid >> 1;          // warp tile: 64m x 32n
  const int m0 = blockIdx.y * 128, n0 = blockIdx.x * 128;
  const int Kc = K / gridDim.z, ks = blockIdx.z * Kc;
  const int NCH = Kc >> 5;
  P += (size_t)blockIdx.z * 256 * N;

  float acc[4][4][4];
  #pragma unroll
  for (int i = 0; i < 4; i++)
    #pragma unroll
    for (int j = 0; j < 4; j++)
      #pragma unroll
      for (int c = 0; c < 4; c++) acc[i][j][c] = 0.f;

  uint4 ra[4], rb[4];
  const __half* aPtr[4];
  const __half* bPtr[4];
  uint32_t stA[4], stB[4];
  #pragma unroll
  for (int j = 0; j < 4; j++) {
    int idx = tid + 256*j;
    int s = idx >> 9, m = (idx >> 2) & 127, q = idx & 3;
    aPtr[j] = A2 + s*aplane + (size_t)(m0 + m)*K + ks + q*8;
    int n = n0 + m; if (n >= N) n = N - 1;     // clamp (cols >= N never stored)
    bPtr[j] = B2 + s*bplane + (size_t)n*K + ks + q*8;
    stA[j] = smbase + s*PT + m*ROWB2 + q*16;
    stB[j] = smbase + 4*PT + s*PT + m*ROWB2 + q*16;
  }

  const uint32_t aOff = (uint32_t)((wm*64 + (lid & 15))*ROWB2 + (lid >> 4)*16);
  const uint32_t bOff = (uint32_t)((wn*32 + (lid & 7) + ((lid >> 4) << 3))*ROWB2
                                   + ((lid >> 3) & 1)*16);
  const int pa[3] = {0, 0, 1};
  const int pb[3] = {0, 1, 0};

  // prolog: chunk 0 -> stage 0
  #pragma unroll
  for (int j = 0; j < 4; j++) { ra[j] = *(const uint4*)aPtr[j]; rb[j] = *(const uint4*)bPtr[j]; }
  #pragma unroll
  for (int j = 0; j < 4; j++) {
    *(uint4*)(smem + (stA[j] - smbase)) = ra[j];
    *(uint4*)(smem + (stB[j] - smbase)) = rb[j];
  }
  __syncthreads();

  for (int ch = 0; ch < NCH; ch++) {
    const int cur = ch & 1;
    const bool hasNext = (ch + 1 < NCH);
    if (hasNext) {
      #pragma unroll
      for (int j = 0; j < 4; j++) {
        ra[j] = *(const uint4*)(aPtr[j] + (ch + 1)*32);
        rb[j] = *(const uint4*)(bPtr[j] + (ch + 1)*32);
      }
    }
    const uint32_t smA = smbase + cur*2*PT;
    const uint32_t smB = smbase + 4*PT + cur*2*PT;
    #pragma unroll
    for (int p = 0; p < 3; p++) {
      const uint32_t aPl = smA + pa[p]*PT + aOff;
      const uint32_t bPl = smB + pb[p]*PT + bOff;
      #pragma unroll
      for (int kk = 0; kk < 2; kk++) {
        uint32_t a[4][4], b[2][4];
        #pragma unroll
        for (int mf = 0; mf < 4; mf++) {
          asm volatile("ldmatrix.sync.aligned.m8n8.x4.shared.b16 {%0,%1,%2,%3}, [%4];"
            : "=r"(a[mf][0]), "=r"(a[mf][1]), "=r"(a[mf][2]), "=r"(a[mf][3])
            : "r"(aPl + mf*(16*ROWB2) + kk*32));
        }
        #pragma unroll
        for (int g = 0; g < 2; g++) {
          asm volatile("ldmatrix.sync.aligned.m8n8.x4.shared.b16 {%0,%1,%2,%3}, [%4];"
            : "=r"(b[g][0]), "=r"(b[g][1]), "=r"(b[g][2]), "=r"(b[g][3])
            : "r"(bPl + g*(16*ROWB2) + kk*32));
        }
        #pragma unroll
        for (int mf = 0; mf < 4; mf++)
          #pragma unroll
          for (int nf = 0; nf < 4; nf++) {
            uint32_t b0 = b[nf >> 1][2*(nf & 1)];
            uint32_t b1 = b[nf >> 1][2*(nf & 1) + 1];
            asm volatile(
              "mma.sync.aligned.m16n8k16.row.col.f32.f16.f16.f32 "
              "{%0,%1,%2,%3}, {%4,%5,%6,%7}, {%8,%9}, {%0,%1,%2,%3};"
              : "+f"(acc[mf][nf][0]), "+f"(acc[mf][nf][1]),
                "+f"(acc[mf][nf][2]), "+f"(acc[mf][nf][3])
              : "r"(a[mf][0]), "r"(a[mf][1]), "r"(a[mf][2]), "r"(a[mf][3]),
                "r"(b0), "r"(b1));
          }
      }
    }
    if (hasNext) {
      const int nxt = cur ^ 1;
      #pragma unroll
      for (int j = 0; j < 4; j++) {
        *(uint4*)(smem + (stA[j] - smbase) + nxt*2*PT) = ra[j];
        *(uint4*)(smem + (stB[j] - smbase) + nxt*2*PT) = rb[j];
      }
    }
    __syncthreads();
  }

  const int mr = lid >> 2, nc2 = 2*(lid & 3);
  #pragma unroll
  for (int mf = 0; mf < 4; mf++) {
    int gm = m0 + wm*64 + mf*16 + mr;
    float* r0 = P + (size_t)gm * N;
    float* r1 = P + (size_t)(gm + 8) * N;
    #pragma unroll
    for (int nf = 0; nf < 4; nf++) {
      int gn = n0 + wn*32 + nf*8 + nc2;
      if (gn < N)     { r0[gn]   = acc[mf][nf][0]; r1[gn]   = acc[mf][nf][2]; }
      if (gn + 1 < N) { r0[gn+1] = acc[mf][nf][1]; r1[gn+1] = acc[mf][nf][3]; }
    }
  }
}

// ---------------- rep penalty + top-k + top-p + gumbel sample + embed + fused rms ----
__global__ void sample_kernel(const float* __restrict__ logits, const int* __restrict__ hist,
                              const int* __restrict__ gsp, int step,
                              unsigned k0, unsigned k1,
                              float* __restrict__ out,
                              const float* __restrict__ embed, float* __restrict__ hnext,
                              const float* __restrict__ w_in0,
                              __half* __restrict__ outX, size_t plane,
                              int do_embed) {
  int b = blockIdx.x, t = threadIdx.x;
  __shared__ float sl[VV];
  __shared__ float wk[VV];
  __shared__ float cv[VV];
  __shared__ int   ci[VV];
  __shared__ float rv[256];
  __shared__ int   ri[256];
  __shared__ int   cnt;
  __shared__ float thrS;

  for (int v = t; v < VV; v += 256) sl[v] = logits[(size_t)b*VV + v];
  if (t == 0) cnt = 0;
  __syncthreads();

  int gs = *gsp;
  int w0 = gs - REPW; if (w0 < 0) w0 = 0;
  int wn = gs - w0;
  float cur = 0.f; int tk = -1;
  if (t < wn) { tk = hist[((size_t)b*200 + w0 + t)*CC + step]; cur = sl[tk]; }
  __syncthreads();
  if (t < wn) {
    float nw = (cur < 0.f) ? __fmul_rn(cur, 1.1f) : __fdiv_rn(cur, 1.1f);
    sl[tk] = nw;
  }
  __syncthreads();

  for (int v = t; v < VV; v += 256) { float x = __fdiv_rn(sl[v], 0.8f); sl[v] = x; wk[v] = x; }
  __syncthreads();

  for (int it = 0; it < 30; it++) {
    float bv = -INF_F; int bi = 0;
    for (int v = t; v < VV; v += 256) { float x = wk[v]; if (x > bv) { bv = x; bi = v; } }
    rv[t] = bv; ri[t] = bi; __syncthreads();
    for (int st = 128; st > 0; st >>= 1) {
      if (t < st) { if (rv[t+st] > rv[t]) { rv[t] = rv[t+st]; ri[t] = ri[t+st]; } }
      __syncthreads();
    }
    if (t == 0) { wk[ri[0]] = -INF_F; if (it == 29) thrS = rv[0]; }
    __syncthreads();
  }
  float thr = thrS;

  for (int v = t; v < VV; v += 256) {
    float x = sl[v];
    if (x >= thr) { int p = atomicAdd(&cnt, 1); cv[p] = x; ci[p] = v; }
  }
  __syncthreads();
  int n = cnt;

  if (t == 0) {
    for (int i = 1; i < n; i++) {
      float kv = cv[i]; int ki = ci[i]; int j = i - 1;
      while (j >= 0 && (cv[j] > kv || (cv[j] == kv && ci[j] > ki))) {
        cv[j+1] = cv[j]; ci[j+1] = ci[j]; j--;
      }
      cv[j+1] = kv; ci[j+1] = ki;
    }
    float mx = cv[n-1];
    float total = 0.f;
    for (int j = 0; j < n; j++) { wk[j] = expf(cv[j] - mx); total += wk[j]; }
    float run = 0.f;
    for (int j = 0; j < n; j++) {
      run = __fadd_rn(run, __fdiv_rn(wk[j], total));
      if (run <= 0.4f) cv[j] = -INF_F;
    }
  }
  __syncthreads();

  float bs = -INF_F; int bidx = 0x7fffffff;
  for (int j = t; j < n; j += 256) {
    float x = cv[j];
    if (x > -INF_F) {
      unsigned m = (unsigned)(b*VV + ci[j]);
      unsigned o0, o1;
      threefry2x32(k0, k1, 0u, m, &o0, &o1);
      unsigned bits = o0 ^ o1;
      float u = __uint_as_float((bits >> 9) | 0x3f800000u) - 1.0f;
      u = __fadd_rn(__fmul_rn(u, 1.0f), 1.17549435e-38f);
      u = fmaxf(1.17549435e-38f, u);
      float g = -logf(-logf(u));
      float sc = __fadd_rn(x, g);
      if (sc > bs || (sc == bs && ci[j] < bidx)) { bs = sc; bidx = ci[j]; }
    }
  }
  rv[t] = bs; ri[t] = bidx; __syncthreads();
  for (int st = 128; st > 0; st >>= 1) {
    if (t < st) {
      if (rv[t+st] > rv[t] || (rv[t+st] == rv[t] && ri[t+st] < ri[t])) {
        rv[t] = rv[t+st]; ri[t] = ri[t+st];
      }
    }
    __syncthreads();
  }
  int best = ri[0];
  if (t == 0) out[b*CC + step] = (float)best;

  if (do_embed) {
    const float* e = embed + (size_t)best*HH;
    float sq = 0.f;
    for (int j = t; j < HH; j += 256) {
      float v = e[j];
      hnext[(size_t)b*HH + j] = v;
      sq += v*v;
    }
    rv[t] = sq; __syncthreads();
    for (int st = 128; st > 0; st >>= 1) { if (t < st) rv[t] += rv[t+st]; __syncthreads(); }
    float r = 1.0f / sqrtf(rv[0]*(1.0f/HH) + 1e-6f);
    for (int j = t; j < HH; j += 256) {
      float y = e[j]*r*w_in0[j];
      __half h0, h1; split2(y, h0, h1);
      size_t o = (size_t)b*HH + j;
      outX[o] = h0; outX[plane + o] = h1;
    }
  }
}

// ---------------- driver ----------------
extern "C" void kernel_launch(void* const* d_in, const int* in_sizes, int n_in,
                              void* d_out, int out_size) {
  const float* backbone = (const float*)d_in[0];
  const int*   hist     = (const int*)d_in[1];
  const int*   gsp      = (const int*)d_in[2];
  const float* embed    = (const float*)d_in[3];
  const float* lmh      = (const float*)d_in[4];
  const float* w_in     = (const float*)d_in[5];
  const float* w_v      = (const float*)d_in[8];
  const float* w_o      = (const float*)d_in[11];
  const float* w_post   = (const float*)d_in[12];
  const float* w_g      = (const float*)d_in[13];
  const float* w_u      = (const float*)d_in[14];
  const float* w_d      = (const float*)d_in[15];
  const float* fnorm    = (const float*)d_in[16];
  float* out = (float*)d_out;
  (void)in_sizes; (void)n_in; (void)out_size;

  float *ph, *plog, *pwoP, *ppart;
  __half *px2, *pv2, *pm2, *pwv2, *pwo2, *pgu2, *pwd2, *plm2;
  cudaGetSymbolAddress((void**)&ph,    g_h);
  cudaGetSymbolAddress((void**)&plog,  g_logits);
  cudaGetSymbolAddress((void**)&pwoP,  g_woP);
  cudaGetSymbolAddress((void**)&ppart, g_part);
  cudaGetSymbolAddress((void**)&px2,   g_x2);
  cudaGetSymbolAddress((void**)&pv2,   g_v2);
  cudaGetSymbolAddress((void**)&pm2,   g_m2);
  cudaGetSymbolAddress((void**)&pwv2,  g_wv2);
  cudaGetSymbolAddress((void**)&pwo2,  g_wo2);
  cudaGetSymbolAddress((void**)&pgu2,  g_gu2);
  cudaGetSymbolAddress((void**)&pwd2,  g_wd2);
  cudaGetSymbolAddress((void**)&plm2,  g_lm2);

  cudaFuncSetAttribute(hgemm_kernel, cudaFuncAttributeMaxDynamicSharedMemorySize, HG_SMEM);

  unsigned key0[CC], key1[CC];
  for (int i = 0; i < CC; i++) threefry2x32(0u, 1234u, 0u, (unsigned)i, &key0[i], &key1[i]);

  const size_t PL_X = (size_t)BB*HH, PL_V = (size_t)BB*DKV, PL_M = (size_t)BB*II;
  const size_t PLW_V = (size_t)LL*DKV*HH, PLW_O = (size_t)LL*HH*DKV;
  const size_t PLW_GU = (size_t)LL*8192*HH, PLW_D = (size_t)LL*HH*II;
  const size_t PLW_L = (size_t)CC*VV*HH;

  // ---- precompute ----
  copy_kernel<<<(BB*HH + 255)/256, 256>>>(backbone, ph, BB*HH);
  wop_kernel<<<(LL*DKV*HH + 255)/256, 256>>>(w_o, pwoP);
  dim3 tb(32, 8);
  tsplit_kernel<<<dim3(DKV/32, HH/32, LL), tb>>>(w_v, pwv2, HH, DKV,
      (size_t)HH*DKV, (size_t)DKV*HH, PLW_V);
  tsplit_kernel<<<dim3(HH/32, DKV/32, LL), tb>>>(pwoP, pwo2, DKV, HH,
      (size_t)DKV*HH, (size_t)HH*DKV, PLW_O);
  // gate -> rows [0,4096), up -> rows [4096,8192) of the fused [8192][K] tile
  tsplit_kernel<<<dim3(II/32, HH/32, LL), tb>>>(w_g, pgu2, HH, II,
      (size_t)HH*II, (size_t)8192*HH, PLW_GU);
  tsplit_kernel<<<dim3(II/32, HH/32, LL), tb>>>(w_u, pgu2 + (size_t)II*HH, HH, II,
      (size_t)HH*II, (size_t)8192*HH, PLW_GU);
  tsplit_kernel<<<dim3(HH/32, II/32, LL), tb>>>(w_d, pwd2, II, HH,
      (size_t)II*HH, (size_t)HH*II, PLW_D);
  split_kernel<<<(unsigned)((PLW_L + 255)/256), 256>>>(lmh, plm2, PLW_L, PLW_L);
  rms2_kernel<<<BB, 256>>>(ph, w_in, px2, PL_X);

  const int MN_V = BB*DKV, MN_L = BB*VV;

  for (int i = 0; i < CC; i++) {
    for (int l = 0; l < LL; l++) {
      // v = x @ wv   (N=512, K=1024, S=16 -> 128 CTAs)
      hgemm_kernel<<<dim3(4, 2, 16), 256, HG_SMEM>>>(px2, PL_X,
          pwv2 + (size_t)l*DKV*HH, PLW_V, ppart, DKV, HH);
      reduce_kernel<<<(MN_V/4 + 255)/256, 256>>>(ppart, nullptr, pv2, PL_V, 16, MN_V/4);
      // h += v @ woP (N=1024, K=512, S=16 -> 256 CTAs, Kc=32)
      hgemm_kernel<<<dim3(8, 2, 16), 256, HG_SMEM>>>(pv2, PL_V,
          pwo2 + (size_t)l*HH*DKV, PLW_O, ppart, HH, DKV);
      reduce_rms_kernel<<<BB, 256>>>(ppart, ph, w_post + (size_t)l*HH, px2, PL_X, 16);
      // gate|up fused (N=8192, K=1024, S=2 -> 256 CTAs)
      hgemm_kernel<<<dim3(64, 2, 2), 256, HG_SMEM>>>(px2, PL_X,
          pgu2 + (size_t)l*8192*HH, PLW_GU, ppart, 8192, HH);
      reduce_swiglu_kernel<<<(BB*II + 255)/256, 256>>>(ppart, pm2, PL_M);
      // down (N=1024, K=4096, S=16 -> 256 CTAs) + residual + next rms
      hgemm_kernel<<<dim3(8, 2, 16), 256, HG_SMEM>>>(pm2, PL_M,
          pwd2 + (size_t)l*HH*II, PLW_D, ppart, HH, II);
      const float* wNext = (l < LL - 1) ? (w_in + (size_t)(l + 1)*HH) : fnorm;
      reduce_rms_kernel<<<BB, 256>>>(ppart, ph, wNext, px2, PL_X, 16);
    }
    // lm head (N=1027, K=1024, S=16 -> 288 CTAs)
    hgemm_kernel<<<dim3(9, 2, 16), 256, HG_SMEM>>>(px2, PL_X,
        plm2 + (size_t)i*VV*HH, PLW_L, ppart, VV, HH);
    reduce_kernel<<<(MN_L/4 + 255)/256, 256>>>(ppart, plog, nullptr, 0, 16, MN_L/4);
    int do_embed = (i < CC - 1) ? 1 : 0;
    const float* etab = embed + (size_t)(do_embed ? (i + 1) : 0)*VV*HH;
    sample_kernel<<<BB, 256>>>(plog, hist, gsp, i, key0[i], key1[i], out,
                               etab, ph, w_in, px2, PL_X, do_embed);
  }
}

// round 10
// speedup vs baseline: 1.2733x; 1.2733x over previous
#include <cuda_runtime.h>
#include <cuda_fp16.h>
#include <cstdint>

#define BB 256
#define HH 1024
#define LL 4
#define DKV 512
#define II 4096
#define VV 1027
#define CC 16
#define REPW 50
#define INF_F __int_as_float(0x7f800000)

// ---------------- scratch (device globals; no allocation) ----------------
__device__ float g_h[BB*HH];
__device__ float g_logits[BB*VV];
__device__ float g_woP[LL*DKV*HH];
__device__ float g_part[4210688];              // split-K partials (max 16*256*1027)
__device__ __half g_x2[2*BB*HH];
__device__ __half g_v2[2*BB*DKV];
__device__ __half g_m2[2*BB*II];
__device__ __half g_wv2[(size_t)2*LL*DKV*HH];  // [2][L][N=512][K=1024]
__device__ __half g_wo2[(size_t)2*LL*HH*DKV];  // [2][L][N=1024][K=512]
__device__ __half g_gu2[(size_t)2*LL*8192*HH]; // [2][L][N=8192][K=1024] (gate|up)
__device__ __half g_wd2[(size_t)2*LL*HH*II];   // [2][L][N=1024][K=4096]
__device__ __half g_lm2[(size_t)2*CC*VV*HH];   // [2][C][N=1027][K=1024]

// ---------------- threefry2x32 (JAX exact) ----------------
#define TF_ROUND(x0,x1,r) { x0 += x1; x1 = (x1<<(r))|(x1>>(32-(r))); x1 ^= x0; }
__host__ __device__ __forceinline__ void threefry2x32(unsigned k0, unsigned k1,
                                                      unsigned c0, unsigned c1,
                                                      unsigned* o0, unsigned* o1) {
  unsigned ks2 = k0 ^ k1 ^ 0x1BD11BDAu;
  unsigned x0 = c0 + k0, x1 = c1 + k1;
  TF_ROUND(x0,x1,13) TF_ROUND(x0,x1,15) TF_ROUND(x0,x1,26) TF_ROUND(x0,x1,6)
  x0 += k1;  x1 += ks2 + 1u;
  TF_ROUND(x0,x1,17) TF_ROUND(x0,x1,29) TF_ROUND(x0,x1,16) TF_ROUND(x0,x1,24)
  x0 += ks2; x1 += k0 + 2u;
  TF_ROUND(x0,x1,13) TF_ROUND(x0,x1,15) TF_ROUND(x0,x1,26) TF_ROUND(x0,x1,6)
  x0 += k0;  x1 += k1 + 3u;
  TF_ROUND(x0,x1,17) TF_ROUND(x0,x1,29) TF_ROUND(x0,x1,16) TF_ROUND(x0,x1,24)
  x0 += k1;  x1 += ks2 + 4u;
  TF_ROUND(x0,x1,13) TF_ROUND(x0,x1,15) TF_ROUND(x0,x1,26) TF_ROUND(x0,x1,6)
  x0 += ks2; x1 += k0 + 5u;
  *o0 = x0; *o1 = x1;
}

// ---------------- small kernels ----------------
__global__ void copy_kernel(const float* __restrict__ in, float* __restrict__ out, int n) {
  int i = blockIdx.x*blockDim.x + threadIdx.x;
  if (i < n) out[i] = in[i];
}

__global__ void wop_kernel(const float* __restrict__ wo, float* __restrict__ out) {
  int idx = blockIdx.x*blockDim.x + threadIdx.x;
  if (idx >= LL*DKV*HH) return;
  int l = idx >> 19;
  int rem = idx & 524287;
  int s = rem >> 10, n = rem & 1023;
  int hv = s >> 6, d = s & 63;
  const float* w = wo + ((size_t)l << 20);
  out[idx] = w[((hv*2)*64 + d)*1024 + n] + w[((hv*2+1)*64 + d)*1024 + n];
}

__device__ __forceinline__ void split2(float x, __half& h0, __half& h1) {
  h0 = __float2half_rn(x);
  h1 = __float2half_rn(x - __half2float(h0));
}

// transpose-split: W fp32 [K][N] (layer z) -> O fp16 2 planes of [N][K]
__global__ void tsplit_kernel(const float* __restrict__ W, __half* __restrict__ O,
                              int K, int N, size_t wLS, size_t oLS, size_t plane) {
  __shared__ float tile[32][33];
  const float* Wz = W + (size_t)blockIdx.z * wLS;
  __half* Oz = O + (size_t)blockIdx.z * oLS;
  int kb = blockIdx.y*32, nb = blockIdx.x*32;
  int tx = threadIdx.x, ty = threadIdx.y;
  for (int i = ty; i < 32; i += 8)
    tile[i][tx] = Wz[(size_t)(kb+i)*N + nb + tx];
  __syncthreads();
  for (int i = ty; i < 32; i += 8) {
    __half h0, h1; split2(tile[tx][i], h0, h1);
    size_t o = (size_t)(nb + i)*K + kb + tx;
    Oz[o] = h0; Oz[plane + o] = h1;
  }
}

// plain split (already [N][K])
__global__ void split_kernel(const float* __restrict__ in, __half* __restrict__ O,
                             size_t n, size_t plane) {
  size_t i = (size_t)blockIdx.x*blockDim.x + threadIdx.x;
  if (i >= n) return;
  __half h0, h1; split2(in[i], h0, h1);
  O[i] = h0; O[plane + i] = h1;
}

__global__ void rms2_kernel(const float* __restrict__ in, const float* __restrict__ w,
                            __half* __restrict__ O, size_t plane) {
  int b = blockIdx.x, t = threadIdx.x;
  const float* row = in + (size_t)b*HH;
  __shared__ float red[256];
  float s = 0.f;
  #pragma unroll
  for (int j = t; j < HH; j += 256) { float v = row[j]; s += v*v; }
  red[t] = s; __syncthreads();
  for (int st = 128; st > 0; st >>= 1) { if (t < st) red[t] += red[t+st]; __syncthreads(); }
  float r = 1.0f / sqrtf(red[0]*(1.0f/HH) + 1e-6f);
  for (int j = t; j < HH; j += 256) {
    float y = row[j]*r*w[j];
    __half h0, h1; split2(y, h0, h1);
    size_t o = (size_t)b*HH + j;
    O[o] = h0; O[plane + o] = h1;
  }
}

// flat split-K reduce: fp32 out and/or fp16x2 out (used for v and lm)
__global__ void reduce_kernel(const float* __restrict__ P, float* __restrict__ outF,
                              __half* __restrict__ outS, size_t plane,
                              int S, int MN4) {
  int i = blockIdx.x*blockDim.x + threadIdx.x;
  if (i >= MN4) return;
  const float4* P4 = (const float4*)P;
  float4 s = P4[i];
  for (int t = 1; t < S; t++) {
    float4 p = P4[(size_t)t*MN4 + i];
    s.x += p.x; s.y += p.y; s.z += p.z; s.w += p.w;
  }
  if (outF) ((float4*)outF)[i] = s;
  if (outS) {
    float v[4] = {s.x, s.y, s.z, s.w};
    #pragma unroll
    for (int c = 0; c < 4; c++) {
      __half h0, h1; split2(v[c], h0, h1);
      size_t o = (size_t)i*4 + c;
      outS[o] = h0; outS[plane + o] = h1;
    }
  }
}

// fused: split-K reduce + residual -> h update + RMSNorm -> fp16x2 splits
__global__ void reduce_rms_kernel(const float* __restrict__ P, float* __restrict__ h,
                                  const float* __restrict__ w,
                                  __half* __restrict__ outX, size_t plane, int S) {
  int b = blockIdx.x, t = threadIdx.x;
  __shared__ float row[HH];
  __shared__ float red[256];
  const int MN = BB*HH;
  float sq = 0.f;
  for (int j = t; j < HH; j += 256) {
    float s = h[(size_t)b*HH + j];
    for (int z = 0; z < S; z++) s += P[(size_t)z*MN + b*HH + j];
    row[j] = s;
    h[(size_t)b*HH + j] = s;
    sq += s*s;
  }
  red[t] = sq; __syncthreads();
  for (int st = 128; st > 0; st >>= 1) { if (t < st) red[t] += red[t+st]; __syncthreads(); }
  float r = 1.0f / sqrtf(red[0]*(1.0f/HH) + 1e-6f);
  for (int j = t; j < HH; j += 256) {
    float y = row[j]*r*w[j];
    __half h0, h1; split2(y, h0, h1);
    size_t o = (size_t)b*HH + j;
    outX[o] = h0; outX[plane + o] = h1;
  }
}

// fused gate+up reduce (S=2) + swiglu -> m fp16x2 splits
__global__ void reduce_swiglu_kernel(const float* __restrict__ P,
                                     __half* __restrict__ outM, size_t plane) {
  int i = blockIdx.x*blockDim.x + threadIdx.x;
  if (i >= BB*II) return;
  int b = i >> 12, j = i & (II - 1);
  const size_t MN = (size_t)BB*8192;
  size_t gi = (size_t)b*8192 + j;
  float g = P[gi] + P[MN + gi];
  float u = P[gi + II] + P[MN + gi + II];
  float s = __fdiv_rn(1.f, __fadd_rn(1.f, expf(-g)));
  float m = g*s*u;
  __half h0, h1; split2(m, h0, h1);
  outM[i] = h0; outM[plane + i] = h1;
}

// ---------------- HMMA fp16x2-split GEMM, 3-stage smem ring, 2-ahead LDG ----------------
// P[z][256][N] = A @ B^T; A2: 2 fp16 planes [M][K]; B2: 2 fp16 planes [N][K].
// 3 products: (a0,b0), (a0,b1), (a1,b0). CTA 128x128, k-chunk 32.
#define ROWB2 80            // 32 halves (64B) + 16B pad
#define PT    10240         // plane tile bytes: 128*80
#define STG_B (4*PT)        // bytes per stage: A planes @0,PT; B planes @2PT,3PT
#define HG_SMEM (3*STG_B)   // 122880

__global__ void __launch_bounds__(256, 1)
hgemm_kernel(const __half* __restrict__ A2, const size_t aplane,
             const __half* __restrict__ B2, const size_t bplane,
             float* __restrict__ P, const int N, const int K) {
  extern __shared__ char smem[];
  uint32_t smbase;
  asm("{ .reg .u64 t; cvta.to.shared.u64 t, %1; cvt.u32.u64 %0, t; }"
      : "=r"(smbase) : "l"(smem));

  const int tid = threadIdx.x, wid = tid >> 5, lid = tid & 31;
  const int wm = wid & 1, wn = wid >> 1;          // warp tile: 64m x 32n
  const int m0 = blockIdx.y * 128, n0 = blockIdx.x * 128;
  const int Kc = K / gridDim.z, ks = blockIdx.z * Kc;
  const int NCH = Kc >> 5;
  P += (size_t)blockIdx.z * 256 * N;

  float acc[4][4][4];
  #pragma unroll
  for (int i = 0; i < 4; i++)
    #pragma unroll
    for (int j = 0; j < 4; j++)
      #pragma unroll
      for (int c = 0; c < 4; c++) acc[i][j][c] = 0.f;

  const __half* aPtr[4];
  const __half* bPtr[4];
  uint32_t offA[4], offB[4];                      // offsets within a stage
  #pragma unroll
  for (int j = 0; j < 4; j++) {
    int idx = tid + 256*j;
    int s = idx >> 9, m = (idx >> 2) & 127, q = idx & 3;
    aPtr[j] = A2 + s*aplane + (size_t)(m0 + m)*K + ks + q*8;
    int n = n0 + m; if (n >= N) n = N - 1;        // clamp (cols >= N never stored)
    bPtr[j] = B2 + s*bplane + (size_t)n*K + ks + q*8;
    offA[j] = (uint32_t)(s*PT + m*ROWB2 + q*16);
    offB[j] = (uint32_t)(2*PT + s*PT + m*ROWB2 + q*16);
  }

  const uint32_t aOff = (uint32_t)((wm*64 + (lid & 15))*ROWB2 + (lid >> 4)*16);
  const uint32_t bOff = (uint32_t)((wn*32 + (lid & 7) + ((lid >> 4) << 3))*ROWB2
                                   + ((lid >> 3) & 1)*16);

  uint4 R0a[4], R0b[4], R1a[4], R1b[4];

  // prolog: ch0 -> R0 -> stage0; ch1 -> R1
  #pragma unroll
  for (int j = 0; j < 4; j++) { R0a[j] = *(const uint4*)aPtr[j]; R0b[j] = *(const uint4*)bPtr[j]; }
  if (NCH > 1) {
    #pragma unroll
    for (int j = 0; j < 4; j++) {
      R1a[j] = *(const uint4*)(aPtr[j] + 32); R1b[j] = *(const uint4*)(bPtr[j] + 32);
    }
  }
  #pragma unroll
  for (int j = 0; j < 4; j++) {
    *(uint4*)(smem + offA[j]) = R0a[j];
    *(uint4*)(smem + offB[j]) = R0b[j];
  }
  __syncthreads();

  // compute on stage base sb (shared-space address)
  #define HG_COMPUTE(sb) do {                                                  \
    const int pa_[3] = {0, 0, 1};                                              \
    const int pb_[3] = {0, 1, 0};                                              \
    _Pragma("unroll")                                                           \
    for (int p = 0; p < 3; p++) {                                               \
      const uint32_t aPl = (sb) + pa_[p]*PT + aOff;                             \
      const uint32_t bPl = (sb) + 2*PT + pb_[p]*PT + bOff;                      \
      _Pragma("unroll")                                                         \
      for (int kk = 0; kk < 2; kk++) {                                          \
        uint32_t a_[4][4], b_[2][4];                                            \
        _Pragma("unroll")                                                       \
        for (int mf = 0; mf < 4; mf++)                                          \
          asm volatile("ldmatrix.sync.aligned.m8n8.x4.shared.b16 {%0,%1,%2,%3}, [%4];" \
            : "=r"(a_[mf][0]), "=r"(a_[mf][1]), "=r"(a_[mf][2]), "=r"(a_[mf][3])\
            : "r"(aPl + mf*(16*ROWB2) + kk*32));                                \
        _Pragma("unroll")                                                       \
        for (int g = 0; g < 2; g++)                                             \
          asm volatile("ldmatrix.sync.aligned.m8n8.x4.shared.b16 {%0,%1,%2,%3}, [%4];" \
            : "=r"(b_[g][0]), "=r"(b_[g][1]), "=r"(b_[g][2]), "=r"(b_[g][3])    \
            : "r"(bPl + g*(16*ROWB2) + kk*32));                                 \
        _Pragma("unroll")                                                       \
        for (int mf = 0; mf < 4; mf++)                                          \
          _Pragma("unroll")                                                     \
          for (int nf = 0; nf < 4; nf++) {                                      \
            uint32_t bb0 = b_[nf >> 1][2*(nf & 1)];                             \
            uint32_t bb1 = b_[nf >> 1][2*(nf & 1) + 1];                         \
            asm volatile(                                                       \
              "mma.sync.aligned.m16n8k16.row.col.f32.f16.f16.f32 "              \
              "{%0,%1,%2,%3}, {%4,%5,%6,%7}, {%8,%9}, {%0,%1,%2,%3};"           \
              : "+f"(acc[mf][nf][0]), "+f"(acc[mf][nf][1]),                     \
                "+f"(acc[mf][nf][2]), "+f"(acc[mf][nf][3])                      \
              : "r"(a_[mf][0]), "r"(a_[mf][1]), "r"(a_[mf][2]), "r"(a_[mf][3]), \
                "r"(bb0), "r"(bb1));                                            \
          }                                                                     \
      }                                                                         \
    }                                                                           \
  } while (0)

  // step: ldg(ch+2 -> Dst), compute(stage scCur), sts(Sts -> stage scN), sync
  #define HG_STEP(ch, Da, Db, Sa, Sb) do {                                      \
    if ((ch) + 2 < NCH) {                                                       \
      _Pragma("unroll")                                                         \
      for (int j = 0; j < 4; j++) {                                             \
        Da[j] = *(const uint4*)(aPtr[j] + ((ch) + 2)*32);                       \
        Db[j] = *(const uint4*)(bPtr[j] + ((ch) + 2)*32);                       \
      }                                                                         \
    }                                                                           \
    HG_COMPUTE(smbase + scCur*STG_B);                                           \
    int scN = (scCur == 2) ? 0 : scCur + 1;                                     \
    if ((ch) + 1 < NCH) {                                                       \
      _Pragma("unroll")                                                         \
      for (int j = 0; j < 4; j++) {                                             \
        *(uint4*)(smem + scN*STG_B + offA[j]) = Sa[j];                          \
        *(uint4*)(smem + scN*STG_B + offB[j]) = Sb[j];                          \
      }                                                                         \
    }                                                                           \
    __syncthreads();                                                            \
    scCur = scN;                                                                \
  } while (0)

  int scCur = 0;
  for (int ch = 0; ch < NCH; ch += 2) {
    HG_STEP(ch, R0a, R0b, R1a, R1b);
    if (ch + 1 < NCH) HG_STEP(ch + 1, R1a, R1b, R0a, R0b);
  }

  const int mr = lid >> 2, nc2 = 2*(lid & 3);
  #pragma unroll
  for (int mf = 0; mf < 4; mf++) {
    int gm = m0 + wm*64 + mf*16 + mr;
    float* r0 = P + (size_t)gm * N;
    float* r1 = P + (size_t)(gm + 8) * N;
    #pragma unroll
    for (int nf = 0; nf < 4; nf++) {
      int gn = n0 + wn*32 + nf*8 + nc2;
      if (gn < N)     { r0[gn]   = acc[mf][nf][0]; r1[gn]   = acc[mf][nf][2]; }
      if (gn + 1 < N) { r0[gn+1] = acc[mf][nf][1]; r1[gn+1] = acc[mf][nf][3]; }
    }
  }
}

// ---------------- rep penalty + top-k + top-p + gumbel sample + embed + fused rms ----
__global__ void sample_kernel(const float* __restrict__ logits, const int* __restrict__ hist,
                              const int* __restrict__ gsp, int step,
                              unsigned k0, unsigned k1,
                              float* __restrict__ out,
                              const float* __restrict__ embed, float* __restrict__ hnext,
                              const float* __restrict__ w_in0,
                              __half* __restrict__ outX, size_t plane,
                              int do_embed) {
  int b = blockIdx.x, t = threadIdx.x;
  __shared__ float sl[VV];
  __shared__ float wk[VV];
  __shared__ float cv[VV];
  __shared__ int   ci[VV];
  __shared__ float rv[256];
  __shared__ int   ri[256];
  __shared__ int   cnt;
  __shared__ float thrS;

  for (int v = t; v < VV; v += 256) sl[v] = logits[(size_t)b*VV + v];
  if (t == 0) cnt = 0;
  __syncthreads();

  int gs = *gsp;
  int w0 = gs - REPW; if (w0 < 0) w0 = 0;
  int wn = gs - w0;
  float cur = 0.f; int tk = -1;
  if (t < wn) { tk = hist[((size_t)b*200 + w0 + t)*CC + step]; cur = sl[tk]; }
  __syncthreads();
  if (t < wn) {
    float nw = (cur < 0.f) ? __fmul_rn(cur, 1.1f) : __fdiv_rn(cur, 1.1f);
    sl[tk] = nw;
  }
  __syncthreads();

  for (int v = t; v < VV; v += 256) { float x = __fdiv_rn(sl[v], 0.8f); sl[v] = x; wk[v] = x; }
  __syncthreads();

  for (int it = 0; it < 30; it++) {
    float bv = -INF_F; int bi = 0;
    for (int v = t; v < VV; v += 256) { float x = wk[v]; if (x > bv) { bv = x; bi = v; } }
    rv[t] = bv; ri[t] = bi; __syncthreads();
    for (int st = 128; st > 0; st >>= 1) {
      if (t < st) { if (rv[t+st] > rv[t]) { rv[t] = rv[t+st]; ri[t] = ri[t+st]; } }
      __syncthreads();
    }
    if (t == 0) { wk[ri[0]] = -INF_F; if (it == 29) thrS = rv[0]; }
    __syncthreads();
  }
  float thr = thrS;

  for (int v = t; v < VV; v += 256) {
    float x = sl[v];
    if (x >= thr) { int p = atomicAdd(&cnt, 1); cv[p] = x; ci[p] = v; }
  }
  __syncthreads();
  int n = cnt;

  if (t == 0) {
    for (int i = 1; i < n; i++) {
      float kv = cv[i]; int ki = ci[i]; int j = i - 1;
      while (j >= 0 && (cv[j] > kv || (cv[j] == kv && ci[j] > ki))) {
        cv[j+1] = cv[j]; ci[j+1] = ci[j]; j--;
      }
      cv[j+1] = kv; ci[j+1] = ki;
    }
    float mx = cv[n-1];
    float total = 0.f;
    for (int j = 0; j < n; j++) { wk[j] = expf(cv[j] - mx); total += wk[j]; }
    float run = 0.f;
    for (int j = 0; j < n; j++) {
      run = __fadd_rn(run, __fdiv_rn(wk[j], total));
      if (run <= 0.4f) cv[j] = -INF_F;
    }
  }
  __syncthreads();

  float bs = -INF_F; int bidx = 0x7fffffff;
  for (int j = t; j < n; j += 256) {
    float x = cv[j];
    if (x > -INF_F) {
      unsigned m = (unsigned)(b*VV + ci[j]);
      unsigned o0, o1;
      threefry2x32(k0, k1, 0u, m, &o0, &o1);
      unsigned bits = o0 ^ o1;
      float u = __uint_as_float((bits >> 9) | 0x3f800000u) - 1.0f;
      u = __fadd_rn(__fmul_rn(u, 1.0f), 1.17549435e-38f);
      u = fmaxf(1.17549435e-38f, u);
      float g = -logf(-logf(u));
      float sc = __fadd_rn(x, g);
      if (sc > bs || (sc == bs && ci[j] < bidx)) { bs = sc; bidx = ci[j]; }
    }
  }
  rv[t] = bs; ri[t] = bidx; __syncthreads();
  for (int st = 128; st > 0; st >>= 1) {
    if (t < st) {
      if (rv[t+st] > rv[t] || (rv[t+st] == rv[t] && ri[t+st] < ri[t])) {
        rv[t] = rv[t+st]; ri[t] = ri[t+st];
      }
    }
    __syncthreads();
  }
  int best = ri[0];
  if (t == 0) out[b*CC + step] = (float)best;

  if (do_embed) {
    const float* e = embed + (size_t)best*HH;
    float sq = 0.f;
    for (int j = t; j < HH; j += 256) {
      float v = e[j];
      hnext[(size_t)b*HH + j] = v;
      sq += v*v;
    }
    rv[t] = sq; __syncthreads();
    for (int st = 128; st > 0; st >>= 1) { if (t < st) rv[t] += rv[t+st]; __syncthreads(); }
    float r = 1.0f / sqrtf(rv[0]*(1.0f/HH) + 1e-6f);
    for (int j = t; j < HH; j += 256) {
      float y = e[j]*r*w_in0[j];
      __half h0, h1; split2(y, h0, h1);
      size_t o = (size_t)b*HH + j;
      outX[o] = h0; outX[plane + o] = h1;
    }
  }
}

// ---------------- driver ----------------
extern "C" void kernel_launch(void* const* d_in, const int* in_sizes, int n_in,
                              void* d_out, int out_size) {
  const float* backbone = (const float*)d_in[0];
  const int*   hist     = (const int*)d_in[1];
  const int*   gsp      = (const int*)d_in[2];
  const float* embed    = (const float*)d_in[3];
  const float* lmh      = (const float*)d_in[4];
  const float* w_in     = (const float*)d_in[5];
  const float* w_v      = (const float*)d_in[8];
  const float* w_o      = (const float*)d_in[11];
  const float* w_post   = (const float*)d_in[12];
  const float* w_g      = (const float*)d_in[13];
  const float* w_u      = (const float*)d_in[14];
  const float* w_d      = (const float*)d_in[15];
  const float* fnorm    = (const float*)d_in[16];
  float* out = (float*)d_out;
  (void)in_sizes; (void)n_in; (void)out_size;

  float *ph, *plog, *pwoP, *ppart;
  __half *px2, *pv2, *pm2, *pwv2, *pwo2, *pgu2, *pwd2, *plm2;
  cudaGetSymbolAddress((void**)&ph,    g_h);
  cudaGetSymbolAddress((void**)&plog,  g_logits);
  cudaGetSymbolAddress((void**)&pwoP,  g_woP);
  cudaGetSymbolAddress((void**)&ppart, g_part);
  cudaGetSymbolAddress((void**)&px2,   g_x2);
  cudaGetSymbolAddress((void**)&pv2,   g_v2);
  cudaGetSymbolAddress((void**)&pm2,   g_m2);
  cudaGetSymbolAddress((void**)&pwv2,  g_wv2);
  cudaGetSymbolAddress((void**)&pwo2,  g_wo2);
  cudaGetSymbolAddress((void**)&pgu2,  g_gu2);
  cudaGetSymbolAddress((void**)&pwd2,  g_wd2);
  cudaGetSymbolAddress((void**)&plm2,  g_lm2);

  cudaFuncSetAttribute(hgemm_kernel, cudaFuncAttributeMaxDynamicSharedMemorySize, HG_SMEM);

  unsigned key0[CC], key1[CC];
  for (int i = 0; i < CC; i++) threefry2x32(0u, 1234u, 0u, (unsigned)i, &key0[i], &key1[i]);

  const size_t PL_X = (size_t)BB*HH, PL_V = (size_t)BB*DKV, PL_M = (size_t)BB*II;
  const size_t PLW_V = (size_t)LL*DKV*HH, PLW_O = (size_t)LL*HH*DKV;
  const size_t PLW_GU = (size_t)LL*8192*HH, PLW_D = (size_t)LL*HH*II;
  const size_t PLW_L = (size_t)CC*VV*HH;

  // ---- precompute ----
  copy_kernel<<<(BB*HH + 255)/256, 256>>>(backbone, ph, BB*HH);
  wop_kernel<<<(LL*DKV*HH + 255)/256, 256>>>(w_o, pwoP);
  dim3 tb(32, 8);
  tsplit_kernel<<<dim3(DKV/32, HH/32, LL), tb>>>(w_v, pwv2, HH, DKV,
      (size_t)HH*DKV, (size_t)DKV*HH, PLW_V);
  tsplit_kernel<<<dim3(HH/32, DKV/32, LL), tb>>>(pwoP, pwo2, DKV, HH,
      (size_t)DKV*HH, (size_t)HH*DKV, PLW_O);
  tsplit_kernel<<<dim3(II/32, HH/32, LL), tb>>>(w_g, pgu2, HH, II,
      (size_t)HH*II, (size_t)8192*HH, PLW_GU);
  tsplit_kernel<<<dim3(II/32, HH/32, LL), tb>>>(w_u, pgu2 + (size_t)II*HH, HH, II,
      (size_t)HH*II, (size_t)8192*HH, PLW_GU);
  tsplit_kernel<<<dim3(HH/32, II/32, LL), tb>>>(w_d, pwd2, II, HH,
      (size_t)II*HH, (size_t)HH*II, PLW_D);
  split_kernel<<<(unsigned)((PLW_L + 255)/256), 256>>>(lmh, plm2, PLW_L, PLW_L);
  rms2_kernel<<<BB, 256>>>(ph, w_in, px2, PL_X);

  const int MN_V = BB*DKV, MN_L = BB*VV;

  for (int i = 0; i < CC; i++) {
    for (int l = 0; l < LL; l++) {
      // v = x @ wv   (N=512, K=1024, S=16 -> 128 CTAs, NCH=2)
      hgemm_kernel<<<dim3(4, 2, 16), 256, HG_SMEM>>>(px2, PL_X,
          pwv2 + (size_t)l*DKV*HH, PLW_V, ppart, DKV, HH);
      reduce_kernel<<<(MN_V/4 + 255)/256, 256>>>(ppart, nullptr, pv2, PL_V, 16, MN_V/4);
      // h += v @ woP (N=1024, K=512, S=8 -> 128 CTAs, NCH=2)
      hgemm_kernel<<<dim3(8, 2, 8), 256, HG_SMEM>>>(pv2, PL_V,
          pwo2 + (size_t)l*HH*DKV, PLW_O, ppart, HH, DKV);
      reduce_rms_kernel<<<BB, 256>>>(ppart, ph, w_post + (size_t)l*HH, px2, PL_X, 8);
      // gate|up fused (N=8192, K=1024, S=2 -> 256 CTAs, NCH=16)
      hgemm_kernel<<<dim3(64, 2, 2), 256, HG_SMEM>>>(px2, PL_X,
          pgu2 + (size_t)l*8192*HH, PLW_GU, ppart, 8192, HH);
      reduce_swiglu_kernel<<<(BB*II + 255)/256, 256>>>(ppart, pm2, PL_M);
      // down (N=1024, K=4096, S=8 -> 128 CTAs, NCH=16) + residual + next rms
      hgemm_kernel<<<dim3(8, 2, 8), 256, HG_SMEM>>>(pm2, PL_M,
          pwd2 + (size_t)l*HH*II, PLW_D, ppart, HH, II);
      const float* wNext = (l < LL - 1) ? (w_in + (size_t)(l + 1)*HH) : fnorm;
      reduce_rms_kernel<<<BB, 256>>>(ppart, ph, wNext, px2, PL_X, 8);
    }
    // lm head (N=1027, K=1024, S=16 -> 288 CTAs, NCH=2)
    hgemm_kernel<<<dim3(9, 2, 16), 256, HG_SMEM>>>(px2, PL_X,
        plm2 + (size_t)i*VV*HH, PLW_L, ppart, VV, HH);
    reduce_kernel<<<(MN_L/4 + 255)/256, 256>>>(ppart, plog, nullptr, 0, 16, MN_L/4);
    int do_embed = (i < CC - 1) ? 1 : 0;
    const float* etab = embed + (size_t)(do_embed ? (i + 1) : 0)*VV*HH;
    sample_kernel<<<BB, 256>>>(plog, hist, gsp, i, key0[i], key1[i], out,
                               etab, ph, w_in, px2, PL_X, do_embed);
  }
}

// round 12
// speedup vs baseline: 1.3350x; 1.0484x over previous
#include <cuda_runtime.h>
#include <cuda_fp16.h>
#include <cstdint>

#define BB 256
#define HH 1024
#define LL 4
#define DKV 512
#define II 4096
#define VV 1027
#define CC 16
#define REPW 50
#define INF_F __int_as_float(0x7f800000)

// ---------------- scratch (device globals; no allocation) ----------------
__device__ float g_h[BB*HH];
__device__ float g_logits[BB*VV];
__device__ float g_woP[LL*DKV*HH];
__device__ float g_part[8388608];              // split-K partials
__device__ __half g_x2[2*BB*HH];
__device__ __half g_v2[2*BB*DKV];
__device__ __half g_m2[2*BB*II];
__device__ __half g_wv2[(size_t)2*LL*DKV*HH];  // tsplit(wv)  [N=512][K=1024]
__device__ __half g_wo2[(size_t)2*LL*HH*DKV];  // tsplit(woP) [N=1024][K=512]
__device__ __half g_gu2[(size_t)2*LL*8192*HH]; // [N=8192][K=1024] (gate|up)
__device__ __half g_wd2[(size_t)2*LL*HH*II];   // [N=1024][K=4096]
__device__ __half g_lm2[(size_t)2*CC*VV*HH];   // [N=1027][K=1024]

// ---------------- threefry2x32 (JAX exact) ----------------
#define TF_ROUND(x0,x1,r) { x0 += x1; x1 = (x1<<(r))|(x1>>(32-(r))); x1 ^= x0; }
__host__ __device__ __forceinline__ void threefry2x32(unsigned k0, unsigned k1,
                                                      unsigned c0, unsigned c1,
                                                      unsigned* o0, unsigned* o1) {
  unsigned ks2 = k0 ^ k1 ^ 0x1BD11BDAu;
  unsigned x0 = c0 + k0, x1 = c1 + k1;
  TF_ROUND(x0,x1,13) TF_ROUND(x0,x1,15) TF_ROUND(x0,x1,26) TF_ROUND(x0,x1,6)
  x0 += k1;  x1 += ks2 + 1u;
  TF_ROUND(x0,x1,17) TF_ROUND(x0,x1,29) TF_ROUND(x0,x1,16) TF_ROUND(x0,x1,24)
  x0 += ks2; x1 += k0 + 2u;
  TF_ROUND(x0,x1,13) TF_ROUND(x0,x1,15) TF_ROUND(x0,x1,26) TF_ROUND(x0,x1,6)
  x0 += k0;  x1 += k1 + 3u;
  TF_ROUND(x0,x1,17) TF_ROUND(x0,x1,29) TF_ROUND(x0,x1,16) TF_ROUND(x0,x1,24)
  x0 += k1;  x1 += ks2 + 4u;
  TF_ROUND(x0,x1,13) TF_ROUND(x0,x1,15) TF_ROUND(x0,x1,26) TF_ROUND(x0,x1,6)
  x0 += ks2; x1 += k0 + 5u;
  *o0 = x0; *o1 = x1;
}

// ---------------- small kernels ----------------
__global__ void copy_kernel(const float* __restrict__ in, float* __restrict__ out, int n) {
  int i = blockIdx.x*blockDim.x + threadIdx.x;
  if (i < n) out[i] = in[i];
}

__global__ void wop_kernel(const float* __restrict__ wo, float* __restrict__ out) {
  int idx = blockIdx.x*blockDim.x + threadIdx.x;
  if (idx >= LL*DKV*HH) return;
  int l = idx >> 19;
  int rem = idx & 524287;
  int s = rem >> 10, n = rem & 1023;
  int hv = s >> 6, d = s & 63;
  const float* w = wo + ((size_t)l << 20);
  out[idx] = w[((hv*2)*64 + d)*1024 + n] + w[((hv*2+1)*64 + d)*1024 + n];
}

__device__ __forceinline__ void split2(float x, __half& h0, __half& h1) {
  h0 = __float2half_rn(x);
  h1 = __float2half_rn(x - __half2float(h0));
}

// transpose-split: W fp32 [K][N] (slab z) -> O fp16 2 planes of [N][K]
__global__ void tsplit_kernel(const float* __restrict__ W, __half* __restrict__ O,
                              int K, int N, size_t wLS, size_t oLS, size_t plane) {
  __shared__ float tile[32][33];
  const float* Wz = W + (size_t)blockIdx.z * wLS;
  __half* Oz = O + (size_t)blockIdx.z * oLS;
  int kb = blockIdx.y*32, nb = blockIdx.x*32;
  int tx = threadIdx.x, ty = threadIdx.y;
  for (int i = ty; i < 32; i += 8)
    tile[i][tx] = Wz[(size_t)(kb+i)*N + nb + tx];
  __syncthreads();
  for (int i = ty; i < 32; i += 8) {
    __half h0, h1; split2(tile[tx][i], h0, h1);
    size_t o = (size_t)(nb + i)*K + kb + tx;
    Oz[o] = h0; Oz[plane + o] = h1;
  }
}

// plain split (already [N][K])
__global__ void split_kernel(const float* __restrict__ in, __half* __restrict__ O,
                             size_t n, size_t plane) {
  size_t i = (size_t)blockIdx.x*blockDim.x + threadIdx.x;
  if (i >= n) return;
  __half h0, h1; split2(in[i], h0, h1);
  O[i] = h0; O[plane + i] = h1;
}

__global__ void rms2_kernel(const float* __restrict__ in, const float* __restrict__ w,
                            __half* __restrict__ O, size_t plane) {
  int b = blockIdx.x, t = threadIdx.x;
  const float* row = in + (size_t)b*HH;
  __shared__ float red[256];
  float s = 0.f;
  #pragma unroll
  for (int j = t; j < HH; j += 256) { float v = row[j]; s += v*v; }
  red[t] = s; __syncthreads();
  for (int st = 128; st > 0; st >>= 1) { if (t < st) red[t] += red[t+st]; __syncthreads(); }
  float r = 1.0f / sqrtf(red[0]*(1.0f/HH) + 1e-6f);
  for (int j = t; j < HH; j += 256) {
    float y = row[j]*r*w[j];
    __half h0, h1; split2(y, h0, h1);
    size_t o = (size_t)b*HH + j;
    O[o] = h0; O[plane + o] = h1;
  }
}

// flat split-K reduce: fp32 out and/or fp16x2 out (used for v and lm)
__global__ void reduce_kernel(const float* __restrict__ P, float* __restrict__ outF,
                              __half* __restrict__ outS, size_t plane,
                              int S, int MN4) {
  int i = blockIdx.x*blockDim.x + threadIdx.x;
  if (i >= MN4) return;
  const float4* P4 = (const float4*)P;
  float4 s = P4[i];
  for (int t = 1; t < S; t++) {
    float4 p = P4[(size_t)t*MN4 + i];
    s.x += p.x; s.y += p.y; s.z += p.z; s.w += p.w;
  }
  if (outF) ((float4*)outF)[i] = s;
  if (outS) {
    float v[4] = {s.x, s.y, s.z, s.w};
    #pragma unroll
    for (int c = 0; c < 4; c++) {
      __half h0, h1; split2(v[c], h0, h1);
      size_t o = (size_t)i*4 + c;
      outS[o] = h0; outS[plane + o] = h1;
    }
  }
}

// fused: split-K reduce + residual -> h update + RMSNorm -> fp16x2 splits
__global__ void reduce_rms_kernel(const float* __restrict__ P, float* __restrict__ h,
                                  const float* __restrict__ w,
                                  __half* __restrict__ outX, size_t plane, int S) {
  int b = blockIdx.x, t = threadIdx.x;
  __shared__ float row[HH];
  __shared__ float red[256];
  const int MN = BB*HH;
  float sq = 0.f;
  for (int j = t; j < HH; j += 256) {
    float s = h[(size_t)b*HH + j];
    for (int z = 0; z < S; z++) s += P[(size_t)z*MN + b*HH + j];
    row[j] = s;
    h[(size_t)b*HH + j] = s;
    sq += s*s;
  }
  red[t] = sq; __syncthreads();
  for (int st = 128; st > 0; st >>= 1) { if (t < st) red[t] += red[t+st]; __syncthreads(); }
  float r = 1.0f / sqrtf(red[0]*(1.0f/HH) + 1e-6f);
  for (int j = t; j < HH; j += 256) {
    float y = row[j]*r*w[j];
    __half h0, h1; split2(y, h0, h1);
    size_t o = (size_t)b*HH + j;
    outX[o] = h0; outX[plane + o] = h1;
  }
}

// gate|up (S=1 partials) + swiglu -> m fp16x2 splits
__global__ void reduce_swiglu_kernel(const float* __restrict__ P,
                                     __half* __restrict__ outM, size_t plane) {
  int i = blockIdx.x*blockDim.x + threadIdx.x;
  if (i >= BB*II) return;
  int b = i >> 12, j = i & (II - 1);
  size_t gi = (size_t)b*8192 + j;
  float g = P[gi];
  float u = P[gi + II];
  float s = __fdiv_rn(1.f, __fadd_rn(1.f, expf(-g)));
  float m = g*s*u;
  __half h0, h1; split2(m, h0, h1);
  outM[i] = h0; outM[plane + i] = h1;
}

// ---------------- HMMA fp16x2-split GEMM, 3-stage smem ring, 2-ahead LDG ----------------
// P[z][256][N] = A @ B^T; A2: 2 fp16 planes [M][K]; B2: 2 fp16 planes [N][K].
// 3 products: (a0,b0), (a0,b1), (a1,b0). CTA 128x128, k-chunk 32.
#define ROWB2 80            // 32 halves (64B) + 16B pad
#define PT    10240         // plane tile bytes: 128*80
#define STG_B (4*PT)        // bytes per stage
#define HG_SMEM (3*STG_B)   // 122880

__global__ void __launch_bounds__(256, 1)
hgemm_kernel(const __half* __restrict__ A2, const size_t aplane,
             const __half* __restrict__ B2, const size_t bplane,
             float* __restrict__ P, const int N, const int K) {
  extern __shared__ char smem[];
  uint32_t smbase;
  asm("{ .reg .u64 t; cvta.to.shared.u64 t, %1; cvt.u32.u64 %0, t; }"
      : "=r"(smbase) : "l"(smem));

  const int tid = threadIdx.x, wid = tid >> 5, lid = tid & 31;
  const int wm = wid & 1, wn = wid >> 1;          // warp tile: 64m x 32n
  const int m0 = blockIdx.y * 128, n0 = blockIdx.x * 128;
  const int Kc = K / gridDim.z, ks = blockIdx.z * Kc;
  const int NCH = Kc >> 5;
  P += (size_t)blockIdx.z * 256 * N;

  float acc[4][4][4];
  #pragma unroll
  for (int i = 0; i < 4; i++)
    #pragma unroll
    for (int j = 0; j < 4; j++)
      #pragma unroll
      for (int c = 0; c < 4; c++) acc[i][j][c] = 0.f;

  const __half* aPtr[4];
  const __half* bPtr[4];
  uint32_t offA[4], offB[4];
  #pragma unroll
  for (int j = 0; j < 4; j++) {
    int idx = tid + 256*j;
    int s = idx >> 9, m = (idx >> 2) & 127, q = idx & 3;
    aPtr[j] = A2 + s*aplane + (size_t)(m0 + m)*K + ks + q*8;
    int n = n0 + m; if (n >= N) n = N - 1;        // clamp (cols >= N never stored)
    bPtr[j] = B2 + s*bplane + (size_t)n*K + ks + q*8;
    offA[j] = (uint32_t)(s*PT + m*ROWB2 + q*16);
    offB[j] = (uint32_t)(2*PT + s*PT + m*ROWB2 + q*16);
  }

  const uint32_t aOff = (uint32_t)((wm*64 + (lid & 15))*ROWB2 + (lid >> 4)*16);
  const uint32_t bOff = (uint32_t)((wn*32 + (lid & 7) + ((lid >> 4) << 3))*ROWB2
                                   + ((lid >> 3) & 1)*16);

  uint4 R0a[4], R0b[4], R1a[4], R1b[4];

  // prolog: ch0 -> R0 -> stage0; ch1 -> R1
  #pragma unroll
  for (int j = 0; j < 4; j++) { R0a[j] = *(const uint4*)aPtr[j]; R0b[j] = *(const uint4*)bPtr[j]; }
  if (NCH > 1) {
    #pragma unroll
    for (int j = 0; j < 4; j++) {
      R1a[j] = *(const uint4*)(aPtr[j] + 32); R1b[j] = *(const uint4*)(bPtr[j] + 32);
    }
  }
  #pragma unroll
  for (int j = 0; j < 4; j++) {
    *(uint4*)(smem + offA[j]) = R0a[j];
    *(uint4*)(smem + offB[j]) = R0b[j];
  }
  __syncthreads();

  #define HG_COMPUTE(sb) do {                                                  \
    const int pa_[3] = {0, 0, 1};                                              \
    const int pb_[3] = {0, 1, 0};                                              \
    _Pragma("unroll")                                                           \
    for (int p = 0; p < 3; p++) {                                               \
      const uint32_t aPl = (sb) + pa_[p]*PT + aOff;                             \
      const uint32_t bPl = (sb) + 2*PT + pb_[p]*PT + bOff;                      \
      _Pragma("unroll")                                                         \
      for (int kk = 0; kk < 2; kk++) {                                          \
        uint32_t a_[4][4], b_[2][4];                                            \
        _Pragma("unroll")                                                       \
        for (int mf = 0; mf < 4; mf++)                                          \
          asm volatile("ldmatrix.sync.aligned.m8n8.x4.shared.b16 {%0,%1,%2,%3}, [%4];" \
            : "=r"(a_[mf][0]), "=r"(a_[mf][1]), "=r"(a_[mf][2]), "=r"(a_[mf][3])\
            : "r"(aPl + mf*(16*ROWB2) + kk*32));                                \
        _Pragma("unroll")                                                       \
        for (int g = 0; g < 2; g++)                                             \
          asm volatile("ldmatrix.sync.aligned.m8n8.x4.shared.b16 {%0,%1,%2,%3}, [%4];" \
            : "=r"(b_[g][0]), "=r"(b_[g][1]), "=r"(b_[g][2]), "=r"(b_[g][3])    \
            : "r"(bPl + g*(16*ROWB2) + kk*32));                                 \
        _Pragma("unroll")                                                       \
        for (int mf = 0; mf < 4; mf++)                                          \
          _Pragma("unroll")                                                     \
          for (int nf = 0; nf < 4; nf++) {                                      \
            uint32_t bb0 = b_[nf >> 1][2*(nf & 1)];                             \
            uint32_t bb1 = b_[nf >> 1][2*(nf & 1) + 1];                         \
            asm volatile(                                                       \
              "mma.sync.aligned.m16n8k16.row.col.f32.f16.f16.f32 "              \
              "{%0,%1,%2,%3}, {%4,%5,%6,%7}, {%8,%9}, {%0,%1,%2,%3};"           \
              : "+f"(acc[mf][nf][0]), "+f"(acc[mf][nf][1]),                     \
                "+f"(acc[mf][nf][2]), "+f"(acc[mf][nf][3])                      \
              : "r"(a_[mf][0]), "r"(a_[mf][1]), "r"(a_[mf][2]), "r"(a_[mf][3]), \
                "r"(bb0), "r"(bb1));                                            \
          }                                                                     \
      }                                                                         \
    }                                                                           \
  } while (0)

  #define HG_STEP(ch, Da, Db, Sa, Sb) do {                                      \
    if ((ch) + 2 < NCH) {                                                       \
      _Pragma("unroll")                                                         \
      for (int j = 0; j < 4; j++) {                                             \
        Da[j] = *(const uint4*)(aPtr[j] + ((ch) + 2)*32);                       \
        Db[j] = *(const uint4*)(bPtr[j] + ((ch) + 2)*32);                       \
      }                                                                         \
    }                                                                           \
    HG_COMPUTE(smbase + scCur*STG_B);                                           \
    int scN = (scCur == 2) ? 0 : scCur + 1;                                     \
    if ((ch) + 1 < NCH) {                                                       \
      _Pragma("unroll")                                                         \
      for (int j = 0; j < 4; j++) {                                             \
        *(uint4*)(smem + scN*STG_B + offA[j]) = Sa[j];                          \
        *(uint4*)(smem + scN*STG_B + offB[j]) = Sb[j];                          \
      }                                                                         \
    }                                                                           \
    __syncthreads();                                                            \
    scCur = scN;                                                                \
  } while (0)

  int scCur = 0;
  for (int ch = 0; ch < NCH; ch += 2) {
    HG_STEP(ch, R0a, R0b, R1a, R1b);
    if (ch + 1 < NCH) HG_STEP(ch + 1, R1a, R1b, R0a, R0b);
  }

  const int mr = lid >> 2, nc2 = 2*(lid & 3);
  #pragma unroll
  for (int mf = 0; mf < 4; mf++) {
    int gm = m0 + wm*64 + mf*16 + mr;
    float* r0 = P + (size_t)gm * N;
    float* r1 = P + (size_t)(gm + 8) * N;
    #pragma unroll
    for (int nf = 0; nf < 4; nf++) {
      int gn = n0 + wn*32 + nf*8 + nc2;
      if (gn < N)     { r0[gn]   = acc[mf][nf][0]; r1[gn]   = acc[mf][nf][2]; }
      if (gn + 1 < N) { r0[gn+1] = acc[mf][nf][1]; r1[gn+1] = acc[mf][nf][3]; }
    }
  }
}

// ---------------- rep penalty + top-k + top-p + gumbel sample + embed + fused rms ----
__global__ void sample_kernel(const float* __restrict__ logits, const int* __restrict__ hist,
                              const int* __restrict__ gsp, int step,
                              unsigned k0, unsigned k1,
                              float* __restrict__ out,
                              const float* __restrict__ embed, float* __restrict__ hnext,
                              const float* __restrict__ w_in0,
                              __half* __restrict__ outX, size_t plane,
                              int do_embed) {
  int b = blockIdx.x, t = threadIdx.x;
  __shared__ float sl[VV];
  __shared__ float wk[VV];
  __shared__ float cv[VV];
  __shared__ int   ci[VV];
  __shared__ float rv[256];
  __shared__ int   ri[256];
  __shared__ int   cnt;
  __shared__ float thrS;

  for (int v = t; v < VV; v += 256) sl[v] = logits[(size_t)b*VV + v];
  if (t == 0) cnt = 0;
  __syncthreads();

  int gs = *gsp;
  int w0 = gs - REPW; if (w0 < 0) w0 = 0;
  int wn = gs - w0;
  float cur = 0.f; int tk = -1;
  if (t < wn) { tk = hist[((size_t)b*200 + w0 + t)*CC + step]; cur = sl[tk]; }
  __syncthreads();
  if (t < wn) {
    float nw = (cur < 0.f) ? __fmul_rn(cur, 1.1f) : __fdiv_rn(cur, 1.1f);
    sl[tk] = nw;
  }
  __syncthreads();

  for (int v = t; v < VV; v += 256) { float x = __fdiv_rn(sl[v], 0.8f); sl[v] = x; wk[v] = x; }
  __syncthreads();

  for (int it = 0; it < 30; it++) {
    float bv = -INF_F; int bi = 0;
    for (int v = t; v < VV; v += 256) { float x = wk[v]; if (x > bv) { bv = x; bi = v; } }
    rv[t] = bv; ri[t] = bi; __syncthreads();
    for (int st = 128; st > 0; st >>= 1) {
      if (t < st) { if (rv[t+st] > rv[t]) { rv[t] = rv[t+st]; ri[t] = ri[t+st]; } }
      __syncthreads();
    }
    if (t == 0) { wk[ri[0]] = -INF_F; if (it == 29) thrS = rv[0]; }
    __syncthreads();
  }
  float thr = thrS;

  for (int v = t; v < VV; v += 256) {
    float x = sl[v];
    if (x >= thr) { int p = atomicAdd(&cnt, 1); cv[p] = x; ci[p] = v; }
  }
  __syncthreads();
  int n = cnt;

  if (t == 0) {
    for (int i = 1; i < n; i++) {
      float kv = cv[i]; int ki = ci[i]; int j = i - 1;
      while (j >= 0 && (cv[j] > kv || (cv[j] == kv && ci[j] > ki))) {
        cv[j+1] = cv[j]; ci[j+1] = ci[j]; j--;
      }
      cv[j+1] = kv; ci[j+1] = ki;
    }
    float mx = cv[n-1];
    float total = 0.f;
    for (int j = 0; j < n; j++) { wk[j] = expf(cv[j] - mx); total += wk[j]; }
    float run = 0.f;
    for (int j = 0; j < n; j++) {
      run = __fadd_rn(run, __fdiv_rn(wk[j], total));
      if (run <= 0.4f) cv[j] = -INF_F;
    }
  }
  __syncthreads();

  float bs = -INF_F; int bidx = 0x7fffffff;
  for (int j = t; j < n; j += 256) {
    float x = cv[j];
    if (x > -INF_F) {
      unsigned m = (unsigned)(b*VV + ci[j]);
      unsigned o0, o1;
      threefry2x32(k0, k1, 0u, m, &o0, &o1);
      unsigned bits = o0 ^ o1;
      float u = __uint_as_float((bits >> 9) | 0x3f800000u) - 1.0f;
      u = __fadd_rn(__fmul_rn(u, 1.0f), 1.17549435e-38f);
      u = fmaxf(1.17549435e-38f, u);
      float g = -logf(-logf(u));
      float sc = __fadd_rn(x, g);
      if (sc > bs || (sc == bs && ci[j] < bidx)) { bs = sc; bidx = ci[j]; }
    }
  }
  rv[t] = bs; ri[t] = bidx; __syncthreads();
  for (int st = 128; st > 0; st >>= 1) {
    if (t < st) {
      if (rv[t+st] > rv[t] || (rv[t+st] == rv[t] && ri[t+st] < ri[t])) {
        rv[t] = rv[t+st]; ri[t] = ri[t+st];
      }
    }
    __syncthreads();
  }
  int best = ri[0];
  if (t == 0) out[b*CC + step] = (float)best;

  if (do_embed) {
    const float* e = embed + (size_t)best*HH;
    float sq = 0.f;
    for (int j = t; j < HH; j += 256) {
      float v = e[j];
      hnext[(size_t)b*HH + j] = v;
      sq += v*v;
    }
    rv[t] = sq; __syncthreads();
    for (int st = 128; st > 0; st >>= 1) { if (t < st) rv[t] += rv[t+st]; __syncthreads(); }
    float r = 1.0f / sqrtf(rv[0]*(1.0f/HH) + 1e-6f);
    for (int j = t; j < HH; j += 256) {
      float y = e[j]*r*w_in0[j];
      __half h0, h1; split2(y, h0, h1);
      size_t o = (size_t)b*HH + j;
      outX[o] = h0; outX[plane + o] = h1;
    }
  }
}

// ---------------- driver ----------------
extern "C" void kernel_launch(void* const* d_in, const int* in_sizes, int n_in,
                              void* d_out, int out_size) {
  const float* backbone = (const float*)d_in[0];
  const int*   hist     = (const int*)d_in[1];
  const int*   gsp      = (const int*)d_in[2];
  const float* embed    = (const float*)d_in[3];
  const float* lmh      = (const float*)d_in[4];
  const float* w_in     = (const float*)d_in[5];
  const float* w_v      = (const float*)d_in[8];
  const float* w_o      = (const float*)d_in[11];
  const float* w_post   = (const float*)d_in[12];
  const float* w_g      = (const float*)d_in[13];
  const float* w_u      = (const float*)d_in[14];
  const float* w_d      = (const float*)d_in[15];
  const float* fnorm    = (const float*)d_in[16];
  float* out = (float*)d_out;
  (void)in_sizes; (void)n_in; (void)out_size;

  float *ph, *plog, *pwoP, *ppart;
  __half *px2, *pv2, *pm2, *pwv2, *pwo2, *pgu2, *pwd2, *plm2;
  cudaGetSymbolAddress((void**)&ph,    g_h);
  cudaGetSymbolAddress((void**)&plog,  g_logits);
  cudaGetSymbolAddress((void**)&pwoP,  g_woP);
  cudaGetSymbolAddress((void**)&ppart, g_part);
  cudaGetSymbolAddress((void**)&px2,   g_x2);
  cudaGetSymbolAddress((void**)&pv2,   g_v2);
  cudaGetSymbolAddress((void**)&pm2,   g_m2);
  cudaGetSymbolAddress((void**)&pwv2,  g_wv2);
  cudaGetSymbolAddress((void**)&pwo2,  g_wo2);
  cudaGetSymbolAddress((void**)&pgu2,  g_gu2);
  cudaGetSymbolAddress((void**)&pwd2,  g_wd2);
  cudaGetSymbolAddress((void**)&plm2,  g_lm2);

  cudaFuncSetAttribute(hgemm_kernel, cudaFuncAttributeMaxDynamicSharedMemorySize, HG_SMEM);

  unsigned key0[CC], key1[CC];
  for (int i = 0; i < CC; i++) threefry2x32(0u, 1234u, 0u, (unsigned)i, &key0[i], &key1[i]);

  const size_t PL_X = (size_t)BB*HH, PL_V = (size_t)BB*DKV, PL_M = (size_t)BB*II;
  const size_t PLW_V = (size_t)LL*DKV*HH, PLW_O = (size_t)LL*HH*DKV;
  const size_t PLW_GU = (size_t)LL*8192*HH, PLW_D = (size_t)LL*HH*II;
  const size_t PLW_L = (size_t)CC*VV*HH;

  // ---- precompute, ordered so launch index 5 is the first step hgemm ----
  copy_kernel<<<(BB*HH + 255)/256, 256>>>(backbone, ph, BB*HH);                 // 0
  wop_kernel<<<(LL*DKV*HH + 255)/256, 256>>>(w_o, pwoP);                        // 1
  dim3 tb(32, 8);
  tsplit_kernel<<<dim3(DKV/32, HH/32, LL), tb>>>(w_v, pwv2, HH, DKV,            // 2
      (size_t)HH*DKV, (size_t)DKV*HH, PLW_V);
  tsplit_kernel<<<dim3(HH/32, DKV/32, LL), tb>>>(pwoP, pwo2, DKV, HH,           // 3
      (size_t)DKV*HH, (size_t)HH*DKV, PLW_O);
  rms2_kernel<<<BB, 256>>>(ph, w_in, px2, PL_X);                                // 4

  const int MN_V = BB*DKV, MN_L = BB*VV;

  // first v-GEMM (step 0, layer 0) lands at capture index 5
  hgemm_kernel<<<dim3(4, 2, 16), 256, HG_SMEM>>>(px2, PL_X,                     // 5 <- ncu
      pwv2, PLW_V, ppart, DKV, HH);
  reduce_kernel<<<(MN_V/4 + 255)/256, 256>>>(ppart, nullptr, pv2, PL_V, 16, MN_V/4);

  // remaining weight splits (before first use; same stream so ordering holds)
  tsplit_kernel<<<dim3(II/32, HH/32, LL), tb>>>(w_g, pgu2, HH, II,
      (size_t)HH*II, (size_t)8192*HH, PLW_GU);
  tsplit_kernel<<<dim3(II/32, HH/32, LL), tb>>>(w_u, pgu2 + (size_t)II*HH, HH, II,
      (size_t)HH*II, (size_t)8192*HH, PLW_GU);
  tsplit_kernel<<<dim3(HH/32, II/32, LL), tb>>>(w_d, pwd2, II, HH,
      (size_t)II*HH, (size_t)HH*II, PLW_D);
  split_kernel<<<(unsigned)((PLW_L + 255)/256), 256>>>(lmh, plm2, PLW_L, PLW_L);

  for (int i = 0; i < CC; i++) {
    for (int l = 0; l < LL; l++) {
      if (!(i == 0 && l == 0)) {
        // v = x @ wv   (N=512, K=1024, S=16 -> 128 CTAs, NCH=2)
        hgemm_kernel<<<dim3(4, 2, 16), 256, HG_SMEM>>>(px2, PL_X,
            pwv2 + (size_t)l*DKV*HH, PLW_V, ppart, DKV, HH);
        reduce_kernel<<<(MN_V/4 + 255)/256, 256>>>(ppart, nullptr, pv2, PL_V, 16, MN_V/4);
      }
      // h += v @ woP (N=1024, K=512, S=8 -> 128 CTAs, NCH=2)
      hgemm_kernel<<<dim3(8, 2, 8), 256, HG_SMEM>>>(pv2, PL_V,
          pwo2 + (size_t)l*HH*DKV, PLW_O, ppart, HH, DKV);
      reduce_rms_kernel<<<BB, 256>>>(ppart, ph, w_post + (size_t)l*HH, px2, PL_X, 8);
      // gate|up fused (N=8192, K=1024, S=1 -> 128 CTAs, NCH=32)
      hgemm_kernel<<<dim3(64, 2, 1), 256, HG_SMEM>>>(px2, PL_X,
          pgu2 + (size_t)l*8192*HH, PLW_GU, ppart, 8192, HH);
      reduce_swiglu_kernel<<<(BB*II + 255)/256, 256>>>(ppart, pm2, PL_M);
      // down (N=1024, K=4096, S=8 -> 128 CTAs, NCH=16) + residual + next rms
      hgemm_kernel<<<dim3(8, 2, 8), 256, HG_SMEM>>>(pm2, PL_M,
          pwd2 + (size_t)l*HH*II, PLW_D, ppart, HH, II);
      const float* wNext = (l < LL - 1) ? (w_in + (size_t)(l + 1)*HH) : fnorm;
      reduce_rms_kernel<<<BB, 256>>>(ppart, ph, wNext, px2, PL_X, 8);
    }
    // lm head (N=1027, K=1024, S=8 -> 144 CTAs, NCH=4)
    hgemm_kernel<<<dim3(9, 2, 8), 256, HG_SMEM>>>(px2, PL_X,
        plm2 + (size_t)i*VV*HH, PLW_L, ppart, VV, HH);
    reduce_kernel<<<(MN_L/4 + 255)/256, 256>>>(ppart, plog, nullptr, 0, 8, MN_L/4);
    int do_embed = (i < CC - 1) ? 1 : 0;
    const float* etab = embed + (size_t)(do_embed ? (i + 1) : 0)*VV*HH;
    sample_kernel<<<BB, 256>>>(plog, hist, gsp, i, key0[i], key1[i], out,
                               etab, ph, w_in, px2, PL_X, do_embed);
  }
}

// round 13
// speedup vs baseline: 1.3457x; 1.0080x over previous
#include <cuda_runtime.h>
#include <cuda_fp16.h>
#include <cstdint>

#define BB 256
#define HH 1024
#define LL 4
#define DKV 512
#define II 4096
#define VV 1027
#define CC 16
#define REPW 50
#define INF_F __int_as_float(0x7f800000)

// ---------------- scratch (device globals; no allocation) ----------------
__device__ float g_h[BB*HH];
__device__ float g_woP[LL*DKV*HH];
__device__ float g_part[8388608];              // split-K partials
__device__ __half g_x2[2*BB*HH];
__device__ __half g_v2[2*BB*DKV];
__device__ __half g_m2[2*BB*II];
__device__ __half g_wv2[(size_t)2*LL*DKV*HH];  // tsplit(wv)  [N=512][K=1024]
__device__ __half g_wo2[(size_t)2*LL*HH*DKV];  // tsplit(woP) [N=1024][K=512]
__device__ __half g_gu2[(size_t)2*LL*8192*HH]; // [N=8192][K=1024] (gate|up)
__device__ __half g_wd2[(size_t)2*LL*HH*II];   // [N=1024][K=4096]
__device__ __half g_lm2[(size_t)2*CC*VV*HH];   // [N=1027][K=1024]

// ---------------- threefry2x32 (JAX exact) ----------------
#define TF_ROUND(x0,x1,r) { x0 += x1; x1 = (x1<<(r))|(x1>>(32-(r))); x1 ^= x0; }
__host__ __device__ __forceinline__ void threefry2x32(unsigned k0, unsigned k1,
                                                      unsigned c0, unsigned c1,
                                                      unsigned* o0, unsigned* o1) {
  unsigned ks2 = k0 ^ k1 ^ 0x1BD11BDAu;
  unsigned x0 = c0 + k0, x1 = c1 + k1;
  TF_ROUND(x0,x1,13) TF_ROUND(x0,x1,15) TF_ROUND(x0,x1,26) TF_ROUND(x0,x1,6)
  x0 += k1;  x1 += ks2 + 1u;
  TF_ROUND(x0,x1,17) TF_ROUND(x0,x1,29) TF_ROUND(x0,x1,16) TF_ROUND(x0,x1,24)
  x0 += ks2; x1 += k0 + 2u;
  TF_ROUND(x0,x1,13) TF_ROUND(x0,x1,15) TF_ROUND(x0,x1,26) TF_ROUND(x0,x1,6)
  x0 += k0;  x1 += k1 + 3u;
  TF_ROUND(x0,x1,17) TF_ROUND(x0,x1,29) TF_ROUND(x0,x1,16) TF_ROUND(x0,x1,24)
  x0 += k1;  x1 += ks2 + 4u;
  TF_ROUND(x0,x1,13) TF_ROUND(x0,x1,15) TF_ROUND(x0,x1,26) TF_ROUND(x0,x1,6)
  x0 += ks2; x1 += k0 + 5u;
  *o0 = x0; *o1 = x1;
}

// ---------------- small kernels ----------------
__global__ void copy_kernel(const float* __restrict__ in, float* __restrict__ out, int n) {
  int i = blockIdx.x*blockDim.x + threadIdx.x;
  if (i < n) out[i] = in[i];
}

__global__ void wop_kernel(const float* __restrict__ wo, float* __restrict__ out) {
  int idx = blockIdx.x*blockDim.x + threadIdx.x;
  if (idx >= LL*DKV*HH) return;
  int l = idx >> 19;
  int rem = idx & 524287;
  int s = rem >> 10, n = rem & 1023;
  int hv = s >> 6, d = s & 63;
  const float* w = wo + ((size_t)l << 20);
  out[idx] = w[((hv*2)*64 + d)*1024 + n] + w[((hv*2+1)*64 + d)*1024 + n];
}

__device__ __forceinline__ void split2(float x, __half& h0, __half& h1) {
  h0 = __float2half_rn(x);
  h1 = __float2half_rn(x - __half2float(h0));
}

// transpose-split: W fp32 [K][N] (slab z) -> O fp16 2 planes of [N][K]
__global__ void tsplit_kernel(const float* __restrict__ W, __half* __restrict__ O,
                              int K, int N, size_t wLS, size_t oLS, size_t plane) {
  __shared__ float tile[32][33];
  const float* Wz = W + (size_t)blockIdx.z * wLS;
  __half* Oz = O + (size_t)blockIdx.z * oLS;
  int kb = blockIdx.y*32, nb = blockIdx.x*32;
  int tx = threadIdx.x, ty = threadIdx.y;
  for (int i = ty; i < 32; i += 8)
    tile[i][tx] = Wz[(size_t)(kb+i)*N + nb + tx];
  __syncthreads();
  for (int i = ty; i < 32; i += 8) {
    __half h0, h1; split2(tile[tx][i], h0, h1);
    size_t o = (size_t)(nb + i)*K + kb + tx;
    Oz[o] = h0; Oz[plane + o] = h1;
  }
}

// plain split (already [N][K])
__global__ void split_kernel(const float* __restrict__ in, __half* __restrict__ O,
                             size_t n, size_t plane) {
  size_t i = (size_t)blockIdx.x*blockDim.x + threadIdx.x;
  if (i >= n) return;
  __half h0, h1; split2(in[i], h0, h1);
  O[i] = h0; O[plane + i] = h1;
}

__global__ void rms2_kernel(const float* __restrict__ in, const float* __restrict__ w,
                            __half* __restrict__ O, size_t plane) {
  int b = blockIdx.x, t = threadIdx.x;
  const float* row = in + (size_t)b*HH;
  __shared__ float red[256];
  float s = 0.f;
  #pragma unroll
  for (int j = t; j < HH; j += 256) { float v = row[j]; s += v*v; }
  red[t] = s; __syncthreads();
  for (int st = 128; st > 0; st >>= 1) { if (t < st) red[t] += red[t+st]; __syncthreads(); }
  float r = 1.0f / sqrtf(red[0]*(1.0f/HH) + 1e-6f);
  for (int j = t; j < HH; j += 256) {
    float y = row[j]*r*w[j];
    __half h0, h1; split2(y, h0, h1);
    size_t o = (size_t)b*HH + j;
    O[o] = h0; O[plane + o] = h1;
  }
}

// flat split-K reduce: fp32 out and/or fp16x2 out (used for v)
__global__ void reduce_kernel(const float* __restrict__ P, float* __restrict__ outF,
                              __half* __restrict__ outS, size_t plane,
                              int S, int MN4) {
  int i = blockIdx.x*blockDim.x + threadIdx.x;
  if (i >= MN4) return;
  const float4* P4 = (const float4*)P;
  float4 s = P4[i];
  for (int t = 1; t < S; t++) {
    float4 p = P4[(size_t)t*MN4 + i];
    s.x += p.x; s.y += p.y; s.z += p.z; s.w += p.w;
  }
  if (outF) ((float4*)outF)[i] = s;
  if (outS) {
    float v[4] = {s.x, s.y, s.z, s.w};
    #pragma unroll
    for (int c = 0; c < 4; c++) {
      __half h0, h1; split2(v[c], h0, h1);
      size_t o = (size_t)i*4 + c;
      outS[o] = h0; outS[plane + o] = h1;
    }
  }
}

// fused: split-K reduce + residual -> h update + RMSNorm -> fp16x2 splits
__global__ void reduce_rms_kernel(const float* __restrict__ P, float* __restrict__ h,
                                  const float* __restrict__ w,
                                  __half* __restrict__ outX, size_t plane, int S) {
  int b = blockIdx.x, t = threadIdx.x;
  __shared__ float row[HH];
  __shared__ float red[256];
  const int MN = BB*HH;
  float sq = 0.f;
  for (int j = t; j < HH; j += 256) {
    float s = h[(size_t)b*HH + j];
    for (int z = 0; z < S; z++) s += P[(size_t)z*MN + b*HH + j];
    row[j] = s;
    h[(size_t)b*HH + j] = s;
    sq += s*s;
  }
  red[t] = sq; __syncthreads();
  for (int st = 128; st > 0; st >>= 1) { if (t < st) red[t] += red[t+st]; __syncthreads(); }
  float r = 1.0f / sqrtf(red[0]*(1.0f/HH) + 1e-6f);
  for (int j = t; j < HH; j += 256) {
    float y = row[j]*r*w[j];
    __half h0, h1; split2(y, h0, h1);
    size_t o = (size_t)b*HH + j;
    outX[o] = h0; outX[plane + o] = h1;
  }
}

// gate|up (S=1 partials) + swiglu -> m fp16x2 splits
__global__ void reduce_swiglu_kernel(const float* __restrict__ P,
                                     __half* __restrict__ outM, size_t plane) {
  int i = blockIdx.x*blockDim.x + threadIdx.x;
  if (i >= BB*II) return;
  int b = i >> 12, j = i & (II - 1);
  size_t gi = (size_t)b*8192 + j;
  float g = P[gi];
  float u = P[gi + II];
  float s = __fdiv_rn(1.f, __fadd_rn(1.f, expf(-g)));
  float m = g*s*u;
  __half h0, h1; split2(m, h0, h1);
  outM[i] = h0; outM[plane + i] = h1;
}

// ---------------- HMMA fp16x2-split GEMM, 3-stage smem ring, 2-ahead LDG ----------------
// P[z][256][N] = A @ B^T; A2: 2 fp16 planes [M][K]; B2: 2 fp16 planes [N][K].
// 3 products: (a0,b0), (a0,b1), (a1,b0). CTA 128x128, k-chunk 32.
#define ROWB2 80            // 32 halves (64B) + 16B pad
#define PT    10240         // plane tile bytes: 128*80
#define STG_B (4*PT)        // bytes per stage
#define HG_SMEM (3*STG_B)   // 122880

__global__ void __launch_bounds__(256, 1)
hgemm_kernel(const __half* __restrict__ A2, const size_t aplane,
             const __half* __restrict__ B2, const size_t bplane,
             float* __restrict__ P, const int N, const int K) {
  extern __shared__ char smem[];
  uint32_t smbase;
  asm("{ .reg .u64 t; cvta.to.shared.u64 t, %1; cvt.u32.u64 %0, t; }"
      : "=r"(smbase) : "l"(smem));

  const int tid = threadIdx.x, wid = tid >> 5, lid = tid & 31;
  const int wm = wid & 1, wn = wid >> 1;          // warp tile: 64m x 32n
  const int m0 = blockIdx.y * 128, n0 = blockIdx.x * 128;
  const int Kc = K / gridDim.z, ks = blockIdx.z * Kc;
  const int NCH = Kc >> 5;
  P += (size_t)blockIdx.z * 256 * N;

  float acc[4][4][4];
  #pragma unroll
  for (int i = 0; i < 4; i++)
    #pragma unroll
    for (int j = 0; j < 4; j++)
      #pragma unroll
      for (int c = 0; c < 4; c++) acc[i][j][c] = 0.f;

  const __half* aPtr[4];
  const __half* bPtr[4];
  uint32_t offA[4], offB[4];
  #pragma unroll
  for (int j = 0; j < 4; j++) {
    int idx = tid + 256*j;
    int s = idx >> 9, m = (idx >> 2) & 127, q = idx & 3;
    aPtr[j] = A2 + s*aplane + (size_t)(m0 + m)*K + ks + q*8;
    int n = n0 + m; if (n >= N) n = N - 1;        // clamp (cols >= N never stored)
    bPtr[j] = B2 + s*bplane + (size_t)n*K + ks + q*8;
    offA[j] = (uint32_t)(s*PT + m*ROWB2 + q*16);
    offB[j] = (uint32_t)(2*PT + s*PT + m*ROWB2 + q*16);
  }

  const uint32_t aOff = (uint32_t)((wm*64 + (lid & 15))*ROWB2 + (lid >> 4)*16);
  const uint32_t bOff = (uint32_t)((wn*32 + (lid & 7) + ((lid >> 4) << 3))*ROWB2
                                   + ((lid >> 3) & 1)*16);

  uint4 R0a[4], R0b[4], R1a[4], R1b[4];

  // prolog: ch0 -> R0 -> stage0; ch1 -> R1
  #pragma unroll
  for (int j = 0; j < 4; j++) { R0a[j] = *(const uint4*)aPtr[j]; R0b[j] = *(const uint4*)bPtr[j]; }
  if (NCH > 1) {
    #pragma unroll
    for (int j = 0; j < 4; j++) {
      R1a[j] = *(const uint4*)(aPtr[j] + 32); R1b[j] = *(const uint4*)(bPtr[j] + 32);
    }
  }
  #pragma unroll
  for (int j = 0; j < 4; j++) {
    *(uint4*)(smem + offA[j]) = R0a[j];
    *(uint4*)(smem + offB[j]) = R0b[j];
  }
  __syncthreads();

  #define HG_COMPUTE(sb) do {                                                  \
    const int pa_[3] = {0, 0, 1};                                              \
    const int pb_[3] = {0, 1, 0};                                              \
    _Pragma("unroll")                                                           \
    for (int p = 0; p < 3; p++) {                                               \
      const uint32_t aPl = (sb) + pa_[p]*PT + aOff;                             \
      const uint32_t bPl = (sb) + 2*PT + pb_[p]*PT + bOff;                      \
      _Pragma("unroll")                                                         \
      for (int kk = 0; kk < 2; kk++) {                                          \
        uint32_t a_[4][4], b_[2][4];                                            \
        _Pragma("unroll")                                                       \
        for (int mf = 0; mf < 4; mf++)                                          \
          asm volatile("ldmatrix.sync.aligned.m8n8.x4.shared.b16 {%0,%1,%2,%3}, [%4];" \
            : "=r"(a_[mf][0]), "=r"(a_[mf][1]), "=r"(a_[mf][2]), "=r"(a_[mf][3])\
            : "r"(aPl + mf*(16*ROWB2) + kk*32));                                \
        _Pragma("unroll")                                                       \
        for (int g = 0; g < 2; g++)                                             \
          asm volatile("ldmatrix.sync.aligned.m8n8.x4.shared.b16 {%0,%1,%2,%3}, [%4];" \
            : "=r"(b_[g][0]), "=r"(b_[g][1]), "=r"(b_[g][2]), "=r"(b_[g][3])    \
            : "r"(bPl + g*(16*ROWB2) + kk*32));                                 \
        _Pragma("unroll")                                                       \
        for (int mf = 0; mf < 4; mf++)                                          \
          _Pragma("unroll")                                                     \
          for (int nf = 0; nf < 4; nf++) {                                      \
            uint32_t bb0 = b_[nf >> 1][2*(nf & 1)];                             \
            uint32_t bb1 = b_[nf >> 1][2*(nf & 1) + 1];                         \
            asm volatile(                                                       \
              "mma.sync.aligned.m16n8k16.row.col.f32.f16.f16.f32 "              \
              "{%0,%1,%2,%3}, {%4,%5,%6,%7}, {%8,%9}, {%0,%1,%2,%3};"           \
              : "+f"(acc[mf][nf][0]), "+f"(acc[mf][nf][1]),                     \
                "+f"(acc[mf][nf][2]), "+f"(acc[mf][nf][3])                      \
              : "r"(a_[mf][0]), "r"(a_[mf][1]), "r"(a_[mf][2]), "r"(a_[mf][3]), \
                "r"(bb0), "r"(bb1));                                            \
          }                                                                     \
      }                                                                         \
    }                                                                           \
  } while (0)

  #define HG_STEP(ch, Da, Db, Sa, Sb) do {                                      \
    if ((ch) + 2 < NCH) {                                                       \
      _Pragma("unroll")                                                         \
      for (int j = 0; j < 4; j++) {                                             \
        Da[j] = *(const uint4*)(aPtr[j] + ((ch) + 2)*32);                       \
        Db[j] = *(const uint4*)(bPtr[j] + ((ch) + 2)*32);                       \
      }                                                                         \
    }                                                                           \
    HG_COMPUTE(smbase + scCur*STG_B);                                           \
    int scN = (scCur == 2) ? 0 : scCur + 1;                                     \
    if ((ch) + 1 < NCH) {                                                       \
      _Pragma("unroll")                                                         \
      for (int j = 0; j < 4; j++) {                                             \
        *(uint4*)(smem + scN*STG_B + offA[j]) = Sa[j];                          \
        *(uint4*)(smem + scN*STG_B + offB[j]) = Sb[j];                          \
      }                                                                         \
    }                                                                           \
    __syncthreads();                                                            \
    scCur = scN;                                                                \
  } while (0)

  int scCur = 0;
  for (int ch = 0; ch < NCH; ch += 2) {
    HG_STEP(ch, R0a, R0b, R1a, R1b);
    if (ch + 1 < NCH) HG_STEP(ch + 1, R1a, R1b, R0a, R0b);
  }

  const int mr = lid >> 2, nc2 = 2*(lid & 3);
  #pragma unroll
  for (int mf = 0; mf < 4; mf++) {
    int gm = m0 + wm*64 + mf*16 + mr;
    float* r0 = P + (size_t)gm * N;
    float* r1 = P + (size_t)(gm + 8) * N;
    #pragma unroll
    for (int nf = 0; nf < 4; nf++) {
      int gn = n0 + wn*32 + nf*8 + nc2;
      if (gn < N)     { r0[gn]   = acc[mf][nf][0]; r1[gn]   = acc[mf][nf][2]; }
      if (gn + 1 < N) { r0[gn+1] = acc[mf][nf][1]; r1[gn+1] = acc[mf][nf][3]; }
    }
  }
}

// ------- rep penalty + top-k + top-p + gumbel sample + embed + fused rms ---------
// Now also fuses the lm-head split-K reduce: reads S partials directly.
__global__ void sample_kernel(const float* __restrict__ P, int S,
                              const int* __restrict__ hist,
                              const int* __restrict__ gsp, int step,
                              unsigned k0, unsigned k1,
                              float* __restrict__ out,
                              const float* __restrict__ embed, float* __restrict__ hnext,
                              const float* __restrict__ w_in0,
                              __half* __restrict__ outX, size_t plane,
                              int do_embed) {
  int b = blockIdx.x, t = threadIdx.x;
  __shared__ float sl[VV];
  __shared__ float wk[VV];
  __shared__ float cv[VV];
  __shared__ int   ci[VV];
  __shared__ float rv[256];
  __shared__ int   ri[256];
  __shared__ int   cnt;
  __shared__ float thrS;

  const int MN = BB*VV;
  for (int v = t; v < VV; v += 256) {
    float s = P[(size_t)b*VV + v];
    for (int z = 1; z < S; z++) s += P[(size_t)z*MN + b*VV + v];
    sl[v] = s;
  }
  if (t == 0) cnt = 0;
  __syncthreads();

  int gs = *gsp;
  int w0 = gs - REPW; if (w0 < 0) w0 = 0;
  int wn = gs - w0;
  float cur = 0.f; int tk = -1;
  if (t < wn) { tk = hist[((size_t)b*200 + w0 + t)*CC + step]; cur = sl[tk]; }
  __syncthreads();
  if (t < wn) {
    float nw = (cur < 0.f) ? __fmul_rn(cur, 1.1f) : __fdiv_rn(cur, 1.1f);
    sl[tk] = nw;
  }
  __syncthreads();

  for (int v = t; v < VV; v += 256) { float x = __fdiv_rn(sl[v], 0.8f); sl[v] = x; wk[v] = x; }
  __syncthreads();

  for (int it = 0; it < 30; it++) {
    float bv = -INF_F; int bi = 0;
    for (int v = t; v < VV; v += 256) { float x = wk[v]; if (x > bv) { bv = x; bi = v; } }
    rv[t] = bv; ri[t] = bi; __syncthreads();
    for (int st = 128; st > 0; st >>= 1) {
      if (t < st) { if (rv[t+st] > rv[t]) { rv[t] = rv[t+st]; ri[t] = ri[t+st]; } }
      __syncthreads();
    }
    if (t == 0) { wk[ri[0]] = -INF_F; if (it == 29) thrS = rv[0]; }
    __syncthreads();
  }
  float thr = thrS;

  for (int v = t; v < VV; v += 256) {
    float x = sl[v];
    if (x >= thr) { int p = atomicAdd(&cnt, 1); cv[p] = x; ci[p] = v; }
  }
  __syncthreads();
  int n = cnt;

  if (t == 0) {
    for (int i = 1; i < n; i++) {
      float kv = cv[i]; int ki = ci[i]; int j = i - 1;
      while (j >= 0 && (cv[j] > kv || (cv[j] == kv && ci[j] > ki))) {
        cv[j+1] = cv[j]; ci[j+1] = ci[j]; j--;
      }
      cv[j+1] = kv; ci[j+1] = ki;
    }
    float mx = cv[n-1];
    float total = 0.f;
    for (int j = 0; j < n; j++) { wk[j] = expf(cv[j] - mx); total += wk[j]; }
    float run = 0.f;
    for (int j = 0; j < n; j++) {
      run = __fadd_rn(run, __fdiv_rn(wk[j], total));
      if (run <= 0.4f) cv[j] = -INF_F;
    }
  }
  __syncthreads();

  float bs = -INF_F; int bidx = 0x7fffffff;
  for (int j = t; j < n; j += 256) {
    float x = cv[j];
    if (x > -INF_F) {
      unsigned m = (unsigned)(b*VV + ci[j]);
      unsigned o0, o1;
      threefry2x32(k0, k1, 0u, m, &o0, &o1);
      unsigned bits = o0 ^ o1;
      float u = __uint_as_float((bits >> 9) | 0x3f800000u) - 1.0f;
      u = __fadd_rn(__fmul_rn(u, 1.0f), 1.17549435e-38f);
      u = fmaxf(1.17549435e-38f, u);
      float g = -logf(-logf(u));
      float sc = __fadd_rn(x, g);
      if (sc > bs || (sc == bs && ci[j] < bidx)) { bs = sc; bidx = ci[j]; }
    }
  }
  rv[t] = bs; ri[t] = bidx; __syncthreads();
  for (int st = 128; st > 0; st >>= 1) {
    if (t < st) {
      if (rv[t+st] > rv[t] || (rv[t+st] == rv[t] && ri[t+st] < ri[t])) {
        rv[t] = rv[t+st]; ri[t] = ri[t+st];
      }
    }
    __syncthreads();
  }
  int best = ri[0];
  if (t == 0) out[b*CC + step] = (float)best;

  if (do_embed) {
    const float* e = embed + (size_t)best*HH;
    float sq = 0.f;
    for (int j = t; j < HH; j += 256) {
      float v = e[j];
      hnext[(size_t)b*HH + j] = v;
      sq += v*v;
    }
    rv[t] = sq; __syncthreads();
    for (int st = 128; st > 0; st >>= 1) { if (t < st) rv[t] += rv[t+st]; __syncthreads(); }
    float r = 1.0f / sqrtf(rv[0]*(1.0f/HH) + 1e-6f);
    for (int j = t; j < HH; j += 256) {
      float y = e[j]*r*w_in0[j];
      __half h0, h1; split2(y, h0, h1);
      size_t o = (size_t)b*HH + j;
      outX[o] = h0; outX[plane + o] = h1;
    }
  }
}

// ---------------- driver ----------------
extern "C" void kernel_launch(void* const* d_in, const int* in_sizes, int n_in,
                              void* d_out, int out_size) {
  const float* backbone = (const float*)d_in[0];
  const int*   hist     = (const int*)d_in[1];
  const int*   gsp      = (const int*)d_in[2];
  const float* embed    = (const float*)d_in[3];
  const float* lmh      = (const float*)d_in[4];
  const float* w_in     = (const float*)d_in[5];
  const float* w_v      = (const float*)d_in[8];
  const float* w_o      = (const float*)d_in[11];
  const float* w_post   = (const float*)d_in[12];
  const float* w_g      = (const float*)d_in[13];
  const float* w_u      = (const float*)d_in[14];
  const float* w_d      = (const float*)d_in[15];
  const float* fnorm    = (const float*)d_in[16];
  float* out = (float*)d_out;
  (void)in_sizes; (void)n_in; (void)out_size;

  float *ph, *pwoP, *ppart;
  __half *px2, *pv2, *pm2, *pwv2, *pwo2, *pgu2, *pwd2, *plm2;
  cudaGetSymbolAddress((void**)&ph,    g_h);
  cudaGetSymbolAddress((void**)&pwoP,  g_woP);
  cudaGetSymbolAddress((void**)&ppart, g_part);
  cudaGetSymbolAddress((void**)&px2,   g_x2);
  cudaGetSymbolAddress((void**)&pv2,   g_v2);
  cudaGetSymbolAddress((void**)&pm2,   g_m2);
  cudaGetSymbolAddress((void**)&pwv2,  g_wv2);
  cudaGetSymbolAddress((void**)&pwo2,  g_wo2);
  cudaGetSymbolAddress((void**)&pgu2,  g_gu2);
  cudaGetSymbolAddress((void**)&pwd2,  g_wd2);
  cudaGetSymbolAddress((void**)&plm2,  g_lm2);

  cudaFuncSetAttribute(hgemm_kernel, cudaFuncAttributeMaxDynamicSharedMemorySize, HG_SMEM);

  unsigned key0[CC], key1[CC];
  for (int i = 0; i < CC; i++) threefry2x32(0u, 1234u, 0u, (unsigned)i, &key0[i], &key1[i]);

  const size_t PL_X = (size_t)BB*HH, PL_V = (size_t)BB*DKV, PL_M = (size_t)BB*II;
  const size_t PLW_V = (size_t)LL*DKV*HH, PLW_O = (size_t)LL*HH*DKV;
  const size_t PLW_GU = (size_t)LL*8192*HH, PLW_D = (size_t)LL*HH*II;
  const size_t PLW_L = (size_t)CC*VV*HH;

  const int MN_V = BB*DKV;
  dim3 tb(32, 8);

  // ---- precompute, ordered so MY launch #3 == overall launch #6 (ncu -s 5 target) ----
  copy_kernel<<<(BB*HH + 255)/256, 256>>>(backbone, ph, BB*HH);                 // my 0
  rms2_kernel<<<BB, 256>>>(ph, w_in, px2, PL_X);                                // my 1
  tsplit_kernel<<<dim3(DKV/32, HH/32, LL), tb>>>(w_v, pwv2, HH, DKV,            // my 2
      (size_t)HH*DKV, (size_t)DKV*HH, PLW_V);
  // first v-GEMM (step 0, layer 0) — profiled by ncu
  hgemm_kernel<<<dim3(4, 2, 16), 256, HG_SMEM>>>(px2, PL_X,                     // my 3
      pwv2, PLW_V, ppart, DKV, HH);
  reduce_kernel<<<(MN_V/4 + 255)/256, 256>>>(ppart, nullptr, pv2, PL_V, 16, MN_V/4);
  // remaining precompute (all before first use; same stream)
  wop_kernel<<<(LL*DKV*HH + 255)/256, 256>>>(w_o, pwoP);
  tsplit_kernel<<<dim3(HH/32, DKV/32, LL), tb>>>(pwoP, pwo2, DKV, HH,
      (size_t)DKV*HH, (size_t)HH*DKV, PLW_O);
  tsplit_kernel<<<dim3(II/32, HH/32, LL), tb>>>(w_g, pgu2, HH, II,
      (size_t)HH*II, (size_t)8192*HH, PLW_GU);
  tsplit_kernel<<<dim3(II/32, HH/32, LL), tb>>>(w_u, pgu2 + (size_t)II*HH, HH, II,
      (size_t)HH*II, (size_t)8192*HH, PLW_GU);
  tsplit_kernel<<<dim3(HH/32, II/32, LL), tb>>>(w_d, pwd2, II, HH,
      (size_t)II*HH, (size_t)HH*II, PLW_D);
  split_kernel<<<(unsigned)((PLW_L + 255)/256), 256>>>(lmh, plm2, PLW_L, PLW_L);

  for (int i = 0; i < CC; i++) {
    for (int l = 0; l < LL; l++) {
      if (!(i == 0 && l == 0)) {
        // v = x @ wv   (N=512, K=1024, S=16 -> 128 CTAs, NCH=2)
        hgemm_kernel<<<dim3(4, 2, 16), 256, HG_SMEM>>>(px2, PL_X,
            pwv2 + (size_t)l*DKV*HH, PLW_V, ppart, DKV, HH);
        reduce_kernel<<<(MN_V/4 + 255)/256, 256>>>(ppart, nullptr, pv2, PL_V, 16, MN_V/4);
      }
      // h += v @ woP (N=1024, K=512, S=8 -> 128 CTAs, NCH=2)
      hgemm_kernel<<<dim3(8, 2, 8), 256, HG_SMEM>>>(pv2, PL_V,
          pwo2 + (size_t)l*HH*DKV, PLW_O, ppart, HH, DKV);
      reduce_rms_kernel<<<BB, 256>>>(ppart, ph, w_post + (size_t)l*HH, px2, PL_X, 8);
      // gate|up fused (N=8192, K=1024, S=1 -> 128 CTAs, NCH=32)
      hgemm_kernel<<<dim3(64, 2, 1), 256, HG_SMEM>>>(px2, PL_X,
          pgu2 + (size_t)l*8192*HH, PLW_GU, ppart, 8192, HH);
      reduce_swiglu_kernel<<<(BB*II + 255)/256, 256>>>(ppart, pm2, PL_M);
      // down (N=1024, K=4096, S=8 -> 128 CTAs, NCH=16) + residual + next rms
      hgemm_kernel<<<dim3(8, 2, 8), 256, HG_SMEM>>>(pm2, PL_M,
          pwd2 + (size_t)l*HH*II, PLW_D, ppart, HH, II);
      const float* wNext = (l < LL - 1) ? (w_in + (size_t)(l + 1)*HH) : fnorm;
      reduce_rms_kernel<<<BB, 256>>>(ppart, ph, wNext, px2, PL_X, 8);
    }
    // lm head (N=1027, K=1024, S=8 -> 144 CTAs, NCH=4); reduce fused into sample
    hgemm_kernel<<<dim3(9, 2, 8), 256, HG_SMEM>>>(px2, PL_X,
        plm2 + (size_t)i*VV*HH, PLW_L, ppart, VV, HH);
    int do_embed = (i < CC - 1) ? 1 : 0;
    const float* etab = embed + (size_t)(do_embed ? (i + 1) : 0)*VV*HH;
    sample_kernel<<<BB, 256>>>(ppart, 8, hist, gsp, i, key0[i], key1[i], out,
                               etab, ph, w_in, px2, PL_X, do_embed);
  }
}